// round 2
// baseline (speedup 1.0000x reference)
#include <cuda_runtime.h>
#include <math.h>

#define BATCH 256
#define MDIM  256
#define VDIM  1024
#define JITTER 1e-6f

// ------------------------- device scratch (no allocs allowed) -------------------------
__device__ float g_W  [(size_t)BATCH * MDIM * VDIM];   // 256 MB : W = L^{-1} A
__device__ float g_L  [(size_t)BATCH * MDIM * MDIM];   // 64 MB  : G, then L (lower)
__device__ float g_Ldi[(size_t)BATCH * 4 * 64 * 64];   // 4 MB   : inv of diag 64x64 blocks of L
__device__ float g_c  [(size_t)BATCH * MDIM];          // L^{-1} b

// ======================= K1: G = A A^T + jitter*I (lower tiles) =======================
__global__ __launch_bounds__(256) void syrk_kernel(const float* __restrict__ A)
{
    __shared__ float AsT[16][68];
    __shared__ float BsT[16][68];
    int t = blockIdx.x, b = blockIdx.y;
    int ti = 0;
    while ((ti + 1) * (ti + 2) / 2 <= t) ti++;
    int tj = t - ti * (ti + 1) / 2;

    const float* Ab = A + (size_t)b * (MDIM * VDIM);
    int tid = threadIdx.x;
    int tx = tid & 15, ty = tid >> 4;
    int lr = tid >> 2, lf = tid & 3;

    float acc[4][4];
#pragma unroll
    for (int i = 0; i < 4; i++)
#pragma unroll
        for (int j = 0; j < 4; j++) acc[i][j] = 0.f;

    for (int k0 = 0; k0 < VDIM; k0 += 16) {
        float4 va = *(const float4*)&Ab[(size_t)(ti * 64 + lr) * VDIM + k0 + 4 * lf];
        float4 vb = *(const float4*)&Ab[(size_t)(tj * 64 + lr) * VDIM + k0 + 4 * lf];
        __syncthreads();
        AsT[4 * lf + 0][lr] = va.x; AsT[4 * lf + 1][lr] = va.y;
        AsT[4 * lf + 2][lr] = va.z; AsT[4 * lf + 3][lr] = va.w;
        BsT[4 * lf + 0][lr] = vb.x; BsT[4 * lf + 1][lr] = vb.y;
        BsT[4 * lf + 2][lr] = vb.z; BsT[4 * lf + 3][lr] = vb.w;
        __syncthreads();
#pragma unroll
        for (int kk = 0; kk < 16; kk++) {
            float4 a4 = *(float4*)&AsT[kk][4 * ty];
            float4 b4 = *(float4*)&BsT[kk][4 * tx];
            float ar[4] = {a4.x, a4.y, a4.z, a4.w};
            float br[4] = {b4.x, b4.y, b4.z, b4.w};
#pragma unroll
            for (int i = 0; i < 4; i++)
#pragma unroll
                for (int j = 0; j < 4; j++) acc[i][j] = fmaf(ar[i], br[j], acc[i][j]);
        }
    }
    float* Gb = g_L + (size_t)b * (MDIM * MDIM);
#pragma unroll
    for (int i = 0; i < 4; i++)
#pragma unroll
        for (int j = 0; j < 4; j++) {
            int gi = ti * 64 + 4 * ty + i;
            int gj = tj * 64 + 4 * tx + j;
            float v = acc[i][j];
            if (gi == gj) v += JITTER;
            Gb[gi * MDIM + gj] = v;
        }
}

// ====== K2: per-batch Cholesky in packed SMEM + diag-block inverses + c = L^{-1} b ======
#define PIDX(i, j) ((i) * ((i) + 1) / 2 + (j))
// smem floats: P 32896 | Inv 4*64*65=16640 | tst 64 | cvec 256  -> 49856 floats
__global__ __launch_bounds__(256) void chol_kernel(const float* __restrict__ b_in)
{
    extern __shared__ float sm2[];
    float* P    = sm2;
    float* Inv  = sm2 + 32896;
    float* tst  = Inv + 4 * 64 * 65;
    float* cvec = tst + 64;

    int b = blockIdx.x, tid = threadIdx.x;
    const float* Gb = g_L + (size_t)b * (MDIM * MDIM);

    { // load lower triangle, one row per thread
        int i = tid, base = PIDX(i, 0);
        for (int j = 0; j <= i; j++) P[base + j] = Gb[i * MDIM + j];
    }
    __syncthreads();

    for (int k = 0; k < MDIM; k++) {
        if (tid == 0) P[PIDX(k, k)] = sqrtf(P[PIDX(k, k)]);
        __syncthreads();
        float dk = P[PIDX(k, k)];
        int i = tid;
        if (i > k) P[PIDX(i, 0) + k] /= dk;
        __syncthreads();
        if (i > k) {
            int base = PIDX(i, 0);
            float lik = P[base + k];
            int jj = PIDX(k + 1, 0);
            for (int j = k + 1; j <= i; j++) {
                P[base + j] = fmaf(-lik, P[jj + k], P[base + j]);
                jj += (j + 1);
            }
        }
        __syncthreads();
    }

    { // invert the four 64x64 lower-triangular diagonal blocks (thread = (block,col))
        int blk = tid >> 6, col = tid & 63, b0 = blk * 64;
        float* Ib = Inv + blk * 64 * 65;
        for (int i = 0; i < col; i++) Ib[i * 65 + col] = 0.f;
        for (int i = col; i < 64; i++) {
            int gi = b0 + i, gbase = PIDX(gi, 0);
            float s = (i == col) ? 1.f : 0.f;
            for (int k = col; k < i; k++) s = fmaf(-P[gbase + b0 + k], Ib[k * 65 + col], s);
            Ib[i * 65 + col] = s / P[gbase + gi];
        }
    }
    __syncthreads();

    { // c = L^{-1} b  (blocked forward substitution using the inverses)
        const float* bv = b_in + (size_t)b * MDIM;
        for (int blk = 0; blk < 4; blk++) {
            if (tid < 64) {
                int gi = blk * 64 + tid, gb = PIDX(gi, 0);
                float s = bv[gi];
                for (int j = 0; j < blk * 64; j++) s = fmaf(-P[gb + j], cvec[j], s);
                tst[tid] = s;
            }
            __syncthreads();
            if (tid < 64) {
                const float* Ib = Inv + blk * 64 * 65 + tid * 65;
                float s = 0.f;
                for (int k = 0; k < 64; k++) s = fmaf(Ib[k], tst[k], s);
                cvec[blk * 64 + tid] = s;
            }
            __syncthreads();
        }
    }

    { // write back L (lower), diag-block inverses, c
        int i = tid, base = PIDX(i, 0);
        float* Lo = g_L + (size_t)b * (MDIM * MDIM) + i * MDIM;
        for (int j = 0; j <= i; j++) Lo[j] = P[base + j];

        int blk = tid >> 6, r = tid & 63;
        const float* Ib = Inv + blk * 64 * 65 + r * 65;
        float* o = g_Ldi + (((size_t)b * 4 + blk) * 64 + r) * 64;
        for (int k = 0; k < 64; k++) o[k] = Ib[k];

        g_c[(size_t)b * MDIM + tid] = cvec[tid];
    }
}

// =================== K3: W = L^{-1} A  (blocked trsm, panel of 128 cols) ===================
// smem floats: Wp 256*128=32768 | Lb 64*68=4352 | Tp 64*128=8192 -> 45312 floats
__global__ __launch_bounds__(256, 1) void trsm_kernel(const float* __restrict__ A)
{
    extern __shared__ float sm3[];
    float* Wp = sm3;
    float* Lb = sm3 + 32768;
    float* Tp = Lb + 64 * 68;

    int vt = blockIdx.x, b = blockIdx.y;
    int vc = vt * 128;
    int tid = threadIdx.x, tx = tid & 15, ty = tid >> 4;
    const float* Ab = A + (size_t)b * (MDIM * VDIM);
    const float* Lg = g_L + (size_t)b * (MDIM * MDIM);
    float* Wg = g_W + (size_t)b * (MDIM * VDIM);

    for (int i = 0; i < 4; i++) {
        float acc[4][8];
#pragma unroll
        for (int rr = 0; rr < 4; rr++)
#pragma unroll
            for (int q = 0; q < 2; q++) {
                float4 av = *(const float4*)&Ab[(size_t)(i * 64 + 4 * ty + rr) * VDIM + vc + 4 * tx + 64 * q];
                acc[rr][4 * q + 0] = av.x; acc[rr][4 * q + 1] = av.y;
                acc[rr][4 * q + 2] = av.z; acc[rr][4 * q + 3] = av.w;
            }
        for (int j = 0; j < i; j++) {
            __syncthreads();
            { // load L block (i,j)
                int r = tid >> 2, f = tid & 3;
#pragma unroll
                for (int s = 0; s < 4; s++) {
                    float4 lv = *(const float4*)&Lg[(i * 64 + r) * MDIM + j * 64 + 16 * f + 4 * s];
                    *(float4*)&Lb[r * 68 + 16 * f + 4 * s] = lv;
                }
            }
            __syncthreads();
            for (int kk = 0; kk < 64; kk++) {
                float a0 = Lb[(4 * ty + 0) * 68 + kk];
                float a1 = Lb[(4 * ty + 1) * 68 + kk];
                float a2 = Lb[(4 * ty + 2) * 68 + kk];
                float a3 = Lb[(4 * ty + 3) * 68 + kk];
                float4 w0 = *(float4*)&Wp[(j * 64 + kk) * 128 + 4 * tx];
                float4 w1 = *(float4*)&Wp[(j * 64 + kk) * 128 + 64 + 4 * tx];
                float ar[4] = {a0, a1, a2, a3};
                float wv[8] = {w0.x, w0.y, w0.z, w0.w, w1.x, w1.y, w1.z, w1.w};
#pragma unroll
                for (int rr = 0; rr < 4; rr++)
#pragma unroll
                    for (int c = 0; c < 8; c++) acc[rr][c] = fmaf(-ar[rr], wv[c], acc[rr][c]);
            }
        }
        __syncthreads();
        // stage acc -> Tp ; load diag-inverse into Lb
#pragma unroll
        for (int rr = 0; rr < 4; rr++)
#pragma unroll
            for (int q = 0; q < 2; q++) {
                float4 o = make_float4(acc[rr][4 * q + 0], acc[rr][4 * q + 1], acc[rr][4 * q + 2], acc[rr][4 * q + 3]);
                *(float4*)&Tp[(4 * ty + rr) * 128 + 4 * tx + 64 * q] = o;
            }
        {
            int r = tid >> 2, f = tid & 3;
#pragma unroll
            for (int s = 0; s < 4; s++) {
                float4 iv = *(const float4*)&g_Ldi[(((size_t)b * 4 + i) * 64 + r) * 64 + 16 * f + 4 * s];
                *(float4*)&Lb[r * 68 + 16 * f + 4 * s] = iv;
            }
        }
        __syncthreads();
#pragma unroll
        for (int rr = 0; rr < 4; rr++)
#pragma unroll
            for (int c = 0; c < 8; c++) acc[rr][c] = 0.f;
        for (int kk = 0; kk < 64; kk++) {
            float a0 = Lb[(4 * ty + 0) * 68 + kk];
            float a1 = Lb[(4 * ty + 1) * 68 + kk];
            float a2 = Lb[(4 * ty + 2) * 68 + kk];
            float a3 = Lb[(4 * ty + 3) * 68 + kk];
            float4 w0 = *(float4*)&Tp[kk * 128 + 4 * tx];
            float4 w1 = *(float4*)&Tp[kk * 128 + 64 + 4 * tx];
            float ar[4] = {a0, a1, a2, a3};
            float wv[8] = {w0.x, w0.y, w0.z, w0.w, w1.x, w1.y, w1.z, w1.w};
#pragma unroll
            for (int rr = 0; rr < 4; rr++)
#pragma unroll
                for (int c = 0; c < 8; c++) acc[rr][c] = fmaf(ar[rr], wv[c], acc[rr][c]);
        }
#pragma unroll
        for (int rr = 0; rr < 4; rr++)
#pragma unroll
            for (int q = 0; q < 2; q++) {
                float4 o = make_float4(acc[rr][4 * q + 0], acc[rr][4 * q + 1], acc[rr][4 * q + 2], acc[rr][4 * q + 3]);
                *(float4*)&Wp[(i * 64 + 4 * ty + rr) * 128 + 4 * tx + 64 * q] = o;
                *(float4*)&Wg[(size_t)(i * 64 + 4 * ty + rr) * VDIM + vc + 4 * tx + 64 * q] = o;
            }
        __syncthreads();
    }
}

// =================== K5: fused ADMM loop (persistent CTA per batch) ===================
// smem floats: rsh 1024 | vp 8*1024 | cc 256 -> 9472 floats = 37888 B
__global__ __launch_bounds__(256, 2) void admm_kernel(
    const float* __restrict__ x_in, const int* __restrict__ mask,
    float* __restrict__ out)
{
    extern __shared__ float sm5[];
    float* rsh = sm5;          // 1024
    float* vp  = sm5 + 1024;   // 8*1024
    float* cc  = sm5 + 9216;   // 256

    int b = blockIdx.x, tid = threadIdx.x;
    int w = tid >> 5, lane = tid & 31;
    const float* Wb = g_W + (size_t)b * (MDIM * VDIM);

    float4 xreg = *(const float4*)&x_in[(size_t)b * VDIM + 4 * tid];
    int4 m4 = *(const int4*)&mask[4 * tid];
    float4 ureg = make_float4(0.f, 0.f, 0.f, 0.f);
    float4 rown = xreg;   // this thread's own 4 entries of r
    cc[tid] = g_c[(size_t)b * MDIM + tid];
    *(float4*)&rsh[4 * tid] = xreg;
    __syncthreads();

    // ---- d pass: d = W^T c (pure axpy over rows) ----
    float4 dreg;
    {
        float4 v[8];
#pragma unroll
        for (int q = 0; q < 8; q++) v[q] = make_float4(0.f, 0.f, 0.f, 0.f);
        for (int j = 0; j < 32; j++) {
            int m = (w << 5) + j;
            const float4* row = (const float4*)(Wb + (size_t)m * VDIM);
            float s = cc[m];
#pragma unroll
            for (int q = 0; q < 8; q++) {
                float4 a = row[lane + 32 * q];
                v[q].x = fmaf(s, a.x, v[q].x); v[q].y = fmaf(s, a.y, v[q].y);
                v[q].z = fmaf(s, a.z, v[q].z); v[q].w = fmaf(s, a.w, v[q].w);
            }
        }
#pragma unroll
        for (int q = 0; q < 8; q++) *(float4*)&vp[w * 1024 + q * 128 + 4 * lane] = v[q];
        __syncthreads();
        dreg = make_float4(0.f, 0.f, 0.f, 0.f);
#pragma unroll
        for (int ww = 0; ww < 8; ww++) {
            float4 p = *(float4*)&vp[ww * 1024 + 4 * tid];
            dreg.x += p.x; dreg.y += p.y; dreg.z += p.z; dreg.w += p.w;
        }
    }

    // ---- 100 ADMM passes + 1 final pass ----
    for (int it = 0; it <= 100; it++) {
        __syncthreads();   // r in SMEM ready; vp free for reuse
        float4 rr[8];
#pragma unroll
        for (int q = 0; q < 8; q++) rr[q] = *(float4*)&rsh[q * 128 + 4 * lane];
        float4 v[8];
#pragma unroll
        for (int q = 0; q < 8; q++) v[q] = make_float4(0.f, 0.f, 0.f, 0.f);

        for (int j = 0; j < 32; j++) {
            int m = (w << 5) + j;
            const float4* row = (const float4*)(Wb + (size_t)m * VDIM);
            float4 a[8];
#pragma unroll
            for (int q = 0; q < 8; q++) a[q] = row[lane + 32 * q];
            float s = 0.f;
#pragma unroll
            for (int q = 0; q < 8; q++) {
                s = fmaf(a[q].x, rr[q].x, s); s = fmaf(a[q].y, rr[q].y, s);
                s = fmaf(a[q].z, rr[q].z, s); s = fmaf(a[q].w, rr[q].w, s);
            }
#pragma unroll
            for (int off = 16; off > 0; off >>= 1) s += __shfl_xor_sync(0xffffffffu, s, off);
#pragma unroll
            for (int q = 0; q < 8; q++) {
                v[q].x = fmaf(s, a[q].x, v[q].x); v[q].y = fmaf(s, a[q].y, v[q].y);
                v[q].z = fmaf(s, a[q].z, v[q].z); v[q].w = fmaf(s, a[q].w, v[q].w);
            }
        }
#pragma unroll
        for (int q = 0; q < 8; q++) *(float4*)&vp[w * 1024 + q * 128 + 4 * lane] = v[q];
        __syncthreads();

        float4 vs = make_float4(0.f, 0.f, 0.f, 0.f);
#pragma unroll
        for (int ww = 0; ww < 8; ww++) {
            float4 p = *(float4*)&vp[ww * 1024 + 4 * tid];
            vs.x += p.x; vs.y += p.y; vs.z += p.z; vs.w += p.w;
        }
        float4 xk;
        xk.x = 0.5f * (rown.x - vs.x) + dreg.x;
        xk.y = 0.5f * (rown.y - vs.y) + dreg.y;
        xk.z = 0.5f * (rown.z - vs.z) + dreg.z;
        xk.w = 0.5f * (rown.w - vs.w) + dreg.w;

        if (it == 100) {
            *(float4*)&out[(size_t)b * VDIM + 4 * tid] = xk;
        } else {
            float wv, zv;
            wv = xk.x + ureg.x; zv = (m4.x > 0) ? fminf(wv, 0.f) : wv; ureg.x = wv - zv; rown.x = xreg.x + zv - ureg.x;
            wv = xk.y + ureg.y; zv = (m4.y > 0) ? fminf(wv, 0.f) : wv; ureg.y = wv - zv; rown.y = xreg.y + zv - ureg.y;
            wv = xk.z + ureg.z; zv = (m4.z > 0) ? fminf(wv, 0.f) : wv; ureg.z = wv - zv; rown.z = xreg.z + zv - ureg.z;
            wv = xk.w + ureg.w; zv = (m4.w > 0) ? fminf(wv, 0.f) : wv; ureg.w = wv - zv; rown.w = xreg.w + zv - ureg.w;
            *(float4*)&rsh[4 * tid] = rown;
        }
    }
}

// ======================================= launch =======================================
extern "C" void kernel_launch(void* const* d_in, const int* in_sizes, int n_in,
                              void* d_out, int out_size)
{
    (void)in_sizes; (void)n_in; (void)out_size;
    const float* x    = (const float*)d_in[0];
    const float* bvec = (const float*)d_in[1];
    const float* A    = (const float*)d_in[2];
    const int*   mask = (const int*)d_in[3];
    float* out = (float*)d_out;

    size_t chol_smem = (size_t)(32896 + 4 * 64 * 65 + 64 + 256) * sizeof(float); // 199424 B
    size_t trsm_smem = (size_t)(32768 + 64 * 68 + 64 * 128) * sizeof(float);     // 181248 B
    size_t admm_smem = (size_t)(1024 + 8 * 1024 + 256) * sizeof(float);          // 37888 B

    cudaFuncSetAttribute((const void*)chol_kernel, cudaFuncAttributeMaxDynamicSharedMemorySize, (int)chol_smem);
    cudaFuncSetAttribute((const void*)trsm_kernel, cudaFuncAttributeMaxDynamicSharedMemorySize, (int)trsm_smem);

    syrk_kernel<<<dim3(10, BATCH), 256>>>(A);
    chol_kernel<<<BATCH, 256, chol_smem>>>(bvec);
    trsm_kernel<<<dim3(8, BATCH), 256, trsm_smem>>>(A);
    admm_kernel<<<BATCH, 256, admm_smem>>>(x, mask, out);
}

// round 3
// speedup vs baseline: 1.0706x; 1.0706x over previous
#include <cuda_runtime.h>
#include <math.h>

#define BATCH 256
#define MDIM  256
#define VDIM  1024
#define JITTER 1e-6f

// ------------------------- device scratch (no allocs allowed) -------------------------
__device__ float g_W  [(size_t)BATCH * MDIM * VDIM];   // 256 MB : W = L^{-1} A
__device__ float g_L  [(size_t)BATCH * MDIM * MDIM];   // 64 MB  : G, then L (lower)
__device__ float g_Ldi[(size_t)BATCH * 4 * 64 * 64];   // 4 MB   : inv of diag 64x64 blocks of L
__device__ float g_c  [(size_t)BATCH * MDIM];          // L^{-1} b

// ======================= K1: G = A A^T + jitter*I (3 lower 128x128 tiles) =======================
// 256 threads = 16x16, 8x8 outputs per thread, k-tile 16, double-buffered SMEM (1 sync/tile).
__global__ __launch_bounds__(256, 2) void syrk_kernel(const float* __restrict__ A)
{
    __shared__ float As[2][16][132];
    __shared__ float Bs[2][16][132];
    int t = blockIdx.x, b = blockIdx.y;
    int ti = (t == 0) ? 0 : 1;
    int tj = (t == 2) ? 1 : 0;

    const float* Abase = A + (size_t)b * (MDIM * VDIM);
    const float* Ai = Abase + (size_t)(ti * 128) * VDIM;
    const float* Aj = Abase + (size_t)(tj * 128) * VDIM;

    int tid = threadIdx.x;
    int tx = tid & 15, ty = tid >> 4;
    int lrow = tid >> 2, lf = tid & 3;      // loader: rows lrow & lrow+64, k-offset 4*lf

    float acc[8][8];
#pragma unroll
    for (int i = 0; i < 8; i++)
#pragma unroll
        for (int j = 0; j < 8; j++) acc[i][j] = 0.f;

    // prologue: tile 0
    float4 pa0 = *(const float4*)&Ai[(size_t)lrow * VDIM + 4 * lf];
    float4 pa1 = *(const float4*)&Ai[(size_t)(lrow + 64) * VDIM + 4 * lf];
    float4 pb0 = *(const float4*)&Aj[(size_t)lrow * VDIM + 4 * lf];
    float4 pb1 = *(const float4*)&Aj[(size_t)(lrow + 64) * VDIM + 4 * lf];
    {
        float va[4] = {pa0.x, pa0.y, pa0.z, pa0.w};
        float vb[4] = {pa1.x, pa1.y, pa1.z, pa1.w};
        float vc[4] = {pb0.x, pb0.y, pb0.z, pb0.w};
        float vd[4] = {pb1.x, pb1.y, pb1.z, pb1.w};
#pragma unroll
        for (int c = 0; c < 4; c++) {
            As[0][4 * lf + c][lrow]      = va[c];
            As[0][4 * lf + c][lrow + 64] = vb[c];
            Bs[0][4 * lf + c][lrow]      = vc[c];
            Bs[0][4 * lf + c][lrow + 64] = vd[c];
        }
    }
    __syncthreads();

    int buf = 0;
    for (int kt = 0; kt < 64; kt++) {
        if (kt < 63) {
            int k0 = (kt + 1) * 16;
            pa0 = *(const float4*)&Ai[(size_t)lrow * VDIM + k0 + 4 * lf];
            pa1 = *(const float4*)&Ai[(size_t)(lrow + 64) * VDIM + k0 + 4 * lf];
            pb0 = *(const float4*)&Aj[(size_t)lrow * VDIM + k0 + 4 * lf];
            pb1 = *(const float4*)&Aj[(size_t)(lrow + 64) * VDIM + k0 + 4 * lf];
        }
#pragma unroll
        for (int kk = 0; kk < 16; kk++) {
            float4 alo = *(const float4*)&As[buf][kk][4 * ty];
            float4 ahi = *(const float4*)&As[buf][kk][64 + 4 * ty];
            float4 blo = *(const float4*)&Bs[buf][kk][4 * tx];
            float4 bhi = *(const float4*)&Bs[buf][kk][64 + 4 * tx];
            float ar[8] = {alo.x, alo.y, alo.z, alo.w, ahi.x, ahi.y, ahi.z, ahi.w};
            float br[8] = {blo.x, blo.y, blo.z, blo.w, bhi.x, bhi.y, bhi.z, bhi.w};
#pragma unroll
            for (int i = 0; i < 8; i++)
#pragma unroll
                for (int j = 0; j < 8; j++) acc[i][j] = fmaf(ar[i], br[j], acc[i][j]);
        }
        if (kt < 63) {
            int nb = buf ^ 1;
            float va[4] = {pa0.x, pa0.y, pa0.z, pa0.w};
            float vb[4] = {pa1.x, pa1.y, pa1.z, pa1.w};
            float vc[4] = {pb0.x, pb0.y, pb0.z, pb0.w};
            float vd[4] = {pb1.x, pb1.y, pb1.z, pb1.w};
#pragma unroll
            for (int c = 0; c < 4; c++) {
                As[nb][4 * lf + c][lrow]      = va[c];
                As[nb][4 * lf + c][lrow + 64] = vb[c];
                Bs[nb][4 * lf + c][lrow]      = vc[c];
                Bs[nb][4 * lf + c][lrow + 64] = vd[c];
            }
            __syncthreads();
            buf = nb;
        }
    }

    float* Gb = g_L + (size_t)b * (MDIM * MDIM);
#pragma unroll
    for (int rr = 0; rr < 8; rr++) {
        int rloc = (rr < 4) ? (4 * ty + rr) : (64 + 4 * ty + rr - 4);
        int grow = ti * 128 + rloc;
#pragma unroll
        for (int q = 0; q < 2; q++) {
            int cloc = 4 * tx + 64 * q;
            float4 v = make_float4(acc[rr][4 * q + 0], acc[rr][4 * q + 1],
                                   acc[rr][4 * q + 2], acc[rr][4 * q + 3]);
            if (ti == tj) {
                int d = rloc - cloc;
                if (d >= 0 && d < 4) ((float*)&v)[d] += JITTER;
            }
            *(float4*)&Gb[(size_t)grow * MDIM + tj * 128 + cloc] = v;
        }
    }
}

// ====== K2: per-batch Cholesky in packed SMEM + diag-block inverses + c = L^{-1} b ======
#define PIDX(i, j) ((i) * ((i) + 1) / 2 + (j))
// smem floats: P 32896 | Inv 16640 | tst 64 | cvec 256 | colk 256 -> 50112 floats
__global__ __launch_bounds__(256) void chol_kernel(const float* __restrict__ b_in)
{
    extern __shared__ float sm2[];
    float* P    = sm2;
    float* Inv  = sm2 + 32896;
    float* tst  = Inv + 4 * 64 * 65;
    float* cvec = tst + 64;
    float* colk = cvec + 256;

    int b = blockIdx.x, tid = threadIdx.x;
    int w = tid >> 5, lane = tid & 31;
    const float* Gb = g_L + (size_t)b * (MDIM * MDIM);

    { // load lower triangle, one row per thread
        int i = tid, base = PIDX(i, 0);
        for (int j = 0; j <= i; j++) P[base + j] = Gb[i * MDIM + j];
    }
    __syncthreads();

    for (int k = 0; k < MDIM; k++) {
        if (tid == 0) P[PIDX(k, k)] = sqrtf(P[PIDX(k, k)]);
        __syncthreads();
        float dk = P[PIDX(k, k)];
        if (tid > k) {
            float v = P[PIDX(tid, 0) + k] / dk;
            P[PIDX(tid, 0) + k] = v;
            colk[tid] = v;
        }
        __syncthreads();
        // rank-1 update: warp-per-row, lanes coalesced over j
        for (int i = k + 1 + w; i < MDIM; i += 8) {
            float lik = colk[i];
            int base = PIDX(i, 0);
            for (int j = k + 1 + lane; j <= i; j += 32)
                P[base + j] = fmaf(-lik, colk[j], P[base + j]);
        }
        __syncthreads();
    }

    { // invert the four 64x64 lower-triangular diagonal blocks (thread = (block,col))
        int blk = tid >> 6, col = tid & 63, b0 = blk * 64;
        float* Ib = Inv + blk * 64 * 65;
        for (int i = 0; i < col; i++) Ib[i * 65 + col] = 0.f;
        for (int i = col; i < 64; i++) {
            int gi = b0 + i, gbase = PIDX(gi, 0);
            float s = (i == col) ? 1.f : 0.f;
            for (int k = col; k < i; k++) s = fmaf(-P[gbase + b0 + k], Ib[k * 65 + col], s);
            Ib[i * 65 + col] = s / P[gbase + gi];
        }
    }
    __syncthreads();

    { // c = L^{-1} b  (blocked forward substitution using the inverses)
        const float* bv = b_in + (size_t)b * MDIM;
        for (int blk = 0; blk < 4; blk++) {
            if (tid < 64) {
                int gi = blk * 64 + tid, gb = PIDX(gi, 0);
                float s = bv[gi];
                for (int j = 0; j < blk * 64; j++) s = fmaf(-P[gb + j], cvec[j], s);
                tst[tid] = s;
            }
            __syncthreads();
            if (tid < 64) {
                const float* Ib = Inv + blk * 64 * 65 + tid * 65;
                float s = 0.f;
                for (int k = 0; k < 64; k++) s = fmaf(Ib[k], tst[k], s);
                cvec[blk * 64 + tid] = s;
            }
            __syncthreads();
        }
    }

    { // write back L (lower), diag-block inverses, c
        int i = tid, base = PIDX(i, 0);
        float* Lo = g_L + (size_t)b * (MDIM * MDIM) + i * MDIM;
        for (int j = 0; j <= i; j++) Lo[j] = P[base + j];

        int blk = tid >> 6, r = tid & 63;
        const float* Ib = Inv + blk * 64 * 65 + r * 65;
        float* o = g_Ldi + (((size_t)b * 4 + blk) * 64 + r) * 64;
        for (int k = 0; k < 64; k++) o[k] = Ib[k];

        g_c[(size_t)b * MDIM + tid] = cvec[tid];
    }
}

// =================== K3: W = L^{-1} A  (blocked trsm; W panel read from global) ===================
// smem floats: Tp 64*132=8448 | { LbT 2*16*68=2176 + Wt 2*16*132=4224 } union { DbT 64*68=4352 }
// total = 8448 + 6400 = 14848 floats = 59392 B  -> 3 CTAs/SM
__global__ __launch_bounds__(256, 2) void trsm_kernel(const float* __restrict__ A)
{
    extern __shared__ float sm3[];
    float* Tp = sm3;             // [64][132]
    float* Lb = sm3 + 8448;      // [2][16][68]
    float* Wt = Lb + 2176;       // [2][16][132]
    float* Db = sm3 + 8448;      // [64][68]  (overlaps Lb/Wt)

    int vt = blockIdx.x, b = blockIdx.y;
    int vc = vt * 128;
    int tid = threadIdx.x, tx = tid & 15, ty = tid >> 4;
    const float* Ab = A + (size_t)b * (MDIM * VDIM);
    const float* Lg = g_L + (size_t)b * (MDIM * MDIM);
    float* Wg = g_W + (size_t)b * (MDIM * VDIM);

    int r4 = tid >> 2, f4 = tid & 3;       // L / Dinv loader
    int kkA = tid >> 5, cg = tid & 31;     // W loader (kkA and kkA+8)

    for (int i = 0; i < 4; i++) {
        float acc[4][8];
#pragma unroll
        for (int r = 0; r < 4; r++)
#pragma unroll
            for (int q = 0; q < 2; q++) {
                float4 av = *(const float4*)&Ab[(size_t)(i * 64 + 4 * ty + r) * VDIM + vc + 4 * tx + 64 * q];
                acc[r][4 * q + 0] = av.x; acc[r][4 * q + 1] = av.y;
                acc[r][4 * q + 2] = av.z; acc[r][4 * q + 3] = av.w;
            }

        int nkt = 4 * i;   // k-extent = 64*i, tiles of 16
        if (nkt > 0) {
            // prologue k0 = 0
            float4 lv  = *(const float4*)&Lg[(size_t)(i * 64 + r4) * MDIM + 4 * f4];
            float4 wv0 = *(const float4*)&Wg[(size_t)(kkA)     * VDIM + vc + 4 * cg];
            float4 wv1 = *(const float4*)&Wg[(size_t)(kkA + 8) * VDIM + vc + 4 * cg];
            Lb[(4 * f4 + 0) * 68 + r4] = lv.x; Lb[(4 * f4 + 1) * 68 + r4] = lv.y;
            Lb[(4 * f4 + 2) * 68 + r4] = lv.z; Lb[(4 * f4 + 3) * 68 + r4] = lv.w;
            *(float4*)&Wt[kkA * 132 + 4 * cg] = wv0;
            *(float4*)&Wt[(kkA + 8) * 132 + 4 * cg] = wv1;
            __syncthreads();

            int buf = 0;
            for (int kt = 0; kt < nkt; kt++) {
                float4 lvn, wv0n, wv1n;
                if (kt + 1 < nkt) {
                    int k0 = (kt + 1) * 16;
                    lvn  = *(const float4*)&Lg[(size_t)(i * 64 + r4) * MDIM + k0 + 4 * f4];
                    wv0n = *(const float4*)&Wg[(size_t)(k0 + kkA)     * VDIM + vc + 4 * cg];
                    wv1n = *(const float4*)&Wg[(size_t)(k0 + kkA + 8) * VDIM + vc + 4 * cg];
                }
                const float* Lc = Lb + buf * 1088;
                const float* Wc = Wt + buf * 2112;
#pragma unroll
                for (int kk = 0; kk < 16; kk++) {
                    float4 a4 = *(const float4*)&Lc[kk * 68 + 4 * ty];
                    float4 w0 = *(const float4*)&Wc[kk * 132 + 4 * tx];
                    float4 w1 = *(const float4*)&Wc[kk * 132 + 64 + 4 * tx];
                    float ar[4] = {a4.x, a4.y, a4.z, a4.w};
                    float wv[8] = {w0.x, w0.y, w0.z, w0.w, w1.x, w1.y, w1.z, w1.w};
#pragma unroll
                    for (int r = 0; r < 4; r++)
#pragma unroll
                        for (int c = 0; c < 8; c++) acc[r][c] = fmaf(-ar[r], wv[c], acc[r][c]);
                }
                if (kt + 1 < nkt) {
                    int nb = buf ^ 1;
                    float* Ln = Lb + nb * 1088;
                    float* Wn = Wt + nb * 2112;
                    Ln[(4 * f4 + 0) * 68 + r4] = lvn.x; Ln[(4 * f4 + 1) * 68 + r4] = lvn.y;
                    Ln[(4 * f4 + 2) * 68 + r4] = lvn.z; Ln[(4 * f4 + 3) * 68 + r4] = lvn.w;
                    *(float4*)&Wn[kkA * 132 + 4 * cg] = wv0n;
                    *(float4*)&Wn[(kkA + 8) * 132 + 4 * cg] = wv1n;
                    __syncthreads();
                    buf = nb;
                }
            }
            __syncthreads();   // all GEMM smem reads done before Db overwrite
        }

        // stage acc -> Tp
#pragma unroll
        for (int r = 0; r < 4; r++)
#pragma unroll
            for (int q = 0; q < 2; q++) {
                float4 o = make_float4(acc[r][4 * q + 0], acc[r][4 * q + 1],
                                       acc[r][4 * q + 2], acc[r][4 * q + 3]);
                *(float4*)&Tp[(4 * ty + r) * 132 + 4 * tx + 64 * q] = o;
            }
        // load Dinv_i transposed into Db: Db[k][r] = Dinv[r][k]
#pragma unroll
        for (int s = 0; s < 4; s++) {
            int n = tid + 256 * s;
            int r = n >> 4, f = n & 15;
            float4 dv = *(const float4*)&g_Ldi[(((size_t)b * 4 + i) * 64 + r) * 64 + 4 * f];
            Db[(4 * f + 0) * 68 + r] = dv.x; Db[(4 * f + 1) * 68 + r] = dv.y;
            Db[(4 * f + 2) * 68 + r] = dv.z; Db[(4 * f + 3) * 68 + r] = dv.w;
        }
        __syncthreads();

        float acc2[4][8];
#pragma unroll
        for (int r = 0; r < 4; r++)
#pragma unroll
            for (int c = 0; c < 8; c++) acc2[r][c] = 0.f;
#pragma unroll 16
        for (int kk = 0; kk < 64; kk++) {
            float4 a4 = *(const float4*)&Db[kk * 68 + 4 * ty];
            float4 t0 = *(const float4*)&Tp[kk * 132 + 4 * tx];
            float4 t1 = *(const float4*)&Tp[kk * 132 + 64 + 4 * tx];
            float ar[4] = {a4.x, a4.y, a4.z, a4.w};
            float tv[8] = {t0.x, t0.y, t0.z, t0.w, t1.x, t1.y, t1.z, t1.w};
#pragma unroll
            for (int r = 0; r < 4; r++)
#pragma unroll
                for (int c = 0; c < 8; c++) acc2[r][c] = fmaf(ar[r], tv[c], acc2[r][c]);
        }

#pragma unroll
        for (int r = 0; r < 4; r++)
#pragma unroll
            for (int q = 0; q < 2; q++) {
                float4 o = make_float4(acc2[r][4 * q + 0], acc2[r][4 * q + 1],
                                       acc2[r][4 * q + 2], acc2[r][4 * q + 3]);
                *(float4*)&Wg[(size_t)(i * 64 + 4 * ty + r) * VDIM + vc + 4 * tx + 64 * q] = o;
            }
        __syncthreads();   // W rows visible to this CTA; Tp/Db reads complete
    }
}

// =================== K5: fused ADMM loop (persistent CTA per batch, d folded in) ===================
// xk = 0.5*r - sum_m (0.5*s_m - c_m) w_m,   s_m = w_m . r
// smem floats: rsh 1024 | vp 8*1024 | cc 256 -> 9472 floats = 37888 B
__global__ __launch_bounds__(256, 2) void admm_kernel(
    const float* __restrict__ x_in, const int* __restrict__ mask,
    float* __restrict__ out)
{
    extern __shared__ float sm5[];
    float* rsh = sm5;          // 1024
    float* vp  = sm5 + 1024;   // 8*1024
    float* cc  = sm5 + 9216;   // 256

    int b = blockIdx.x, tid = threadIdx.x;
    int w = tid >> 5, lane = tid & 31;
    const float* Wb = g_W + (size_t)b * (MDIM * VDIM);

    float4 xreg = *(const float4*)&x_in[(size_t)b * VDIM + 4 * tid];
    int4 m4 = *(const int4*)&mask[4 * tid];
    float4 ureg = make_float4(0.f, 0.f, 0.f, 0.f);
    float4 rown = xreg;   // this thread's own 4 entries of r
    cc[tid] = g_c[(size_t)b * MDIM + tid];
    *(float4*)&rsh[4 * tid] = xreg;

    for (int it = 0; it <= 100; it++) {
        __syncthreads();   // r in SMEM ready; vp free for reuse
        float4 rr[8];
#pragma unroll
        for (int q = 0; q < 8; q++) rr[q] = *(float4*)&rsh[q * 128 + 4 * lane];
        float4 v[8];
#pragma unroll
        for (int q = 0; q < 8; q++) v[q] = make_float4(0.f, 0.f, 0.f, 0.f);

        for (int j = 0; j < 32; j++) {
            int m = (w << 5) + j;
            const float4* row = (const float4*)(Wb + (size_t)m * VDIM);
            float4 a[8];
#pragma unroll
            for (int q = 0; q < 8; q++) a[q] = row[lane + 32 * q];
            float s = 0.f;
#pragma unroll
            for (int q = 0; q < 8; q++) {
                s = fmaf(a[q].x, rr[q].x, s); s = fmaf(a[q].y, rr[q].y, s);
                s = fmaf(a[q].z, rr[q].z, s); s = fmaf(a[q].w, rr[q].w, s);
            }
#pragma unroll
            for (int off = 16; off > 0; off >>= 1) s += __shfl_xor_sync(0xffffffffu, s, off);
            float coef = 0.5f * s - cc[m];
#pragma unroll
            for (int q = 0; q < 8; q++) {
                v[q].x = fmaf(coef, a[q].x, v[q].x); v[q].y = fmaf(coef, a[q].y, v[q].y);
                v[q].z = fmaf(coef, a[q].z, v[q].z); v[q].w = fmaf(coef, a[q].w, v[q].w);
            }
        }
#pragma unroll
        for (int q = 0; q < 8; q++) *(float4*)&vp[w * 1024 + q * 128 + 4 * lane] = v[q];
        __syncthreads();

        float4 vs = make_float4(0.f, 0.f, 0.f, 0.f);
#pragma unroll
        for (int ww = 0; ww < 8; ww++) {
            float4 p = *(float4*)&vp[ww * 1024 + 4 * tid];
            vs.x += p.x; vs.y += p.y; vs.z += p.z; vs.w += p.w;
        }
        float4 xk;
        xk.x = 0.5f * rown.x - vs.x;
        xk.y = 0.5f * rown.y - vs.y;
        xk.z = 0.5f * rown.z - vs.z;
        xk.w = 0.5f * rown.w - vs.w;

        if (it == 100) {
            *(float4*)&out[(size_t)b * VDIM + 4 * tid] = xk;
        } else {
            float wv, zv;
            wv = xk.x + ureg.x; zv = (m4.x > 0) ? fminf(wv, 0.f) : wv; ureg.x = wv - zv; rown.x = xreg.x + zv - ureg.x;
            wv = xk.y + ureg.y; zv = (m4.y > 0) ? fminf(wv, 0.f) : wv; ureg.y = wv - zv; rown.y = xreg.y + zv - ureg.y;
            wv = xk.z + ureg.z; zv = (m4.z > 0) ? fminf(wv, 0.f) : wv; ureg.z = wv - zv; rown.z = xreg.z + zv - ureg.z;
            wv = xk.w + ureg.w; zv = (m4.w > 0) ? fminf(wv, 0.f) : wv; ureg.w = wv - zv; rown.w = xreg.w + zv - ureg.w;
            *(float4*)&rsh[4 * tid] = rown;
        }
    }
}

// ======================================= launch =======================================
extern "C" void kernel_launch(void* const* d_in, const int* in_sizes, int n_in,
                              void* d_out, int out_size)
{
    (void)in_sizes; (void)n_in; (void)out_size;
    const float* x    = (const float*)d_in[0];
    const float* bvec = (const float*)d_in[1];
    const float* A    = (const float*)d_in[2];
    const int*   mask = (const int*)d_in[3];
    float* out = (float*)d_out;

    size_t chol_smem = (size_t)(32896 + 4 * 64 * 65 + 64 + 256 + 256) * sizeof(float); // 200448 B
    size_t trsm_smem = (size_t)(8448 + 2176 + 4224) * sizeof(float);                   // 59392 B
    size_t admm_smem = (size_t)(1024 + 8 * 1024 + 256) * sizeof(float);                // 37888 B

    cudaFuncSetAttribute((const void*)chol_kernel, cudaFuncAttributeMaxDynamicSharedMemorySize, (int)chol_smem);
    cudaFuncSetAttribute((const void*)trsm_kernel, cudaFuncAttributeMaxDynamicSharedMemorySize, (int)trsm_smem);

    syrk_kernel<<<dim3(3, BATCH), 256>>>(A);
    chol_kernel<<<BATCH, 256, chol_smem>>>(bvec);
    trsm_kernel<<<dim3(8, BATCH), 256, trsm_smem>>>(A);
    admm_kernel<<<BATCH, 256, admm_smem>>>(x, mask, out);
}

// round 4
// speedup vs baseline: 1.1333x; 1.0586x over previous
#include <cuda_runtime.h>
#include <math.h>

#define BATCH 256
#define MDIM  256
#define VDIM  1024
#define JITTER 1e-6f
#define CACHED_WARPS 3   // warps 0..2 -> W rows 0..95 kept L2-resident (96 MB chip-wide)

// ------------------------- device scratch (no allocs allowed) -------------------------
__device__ float g_W  [(size_t)BATCH * MDIM * VDIM];   // 256 MB : W = L^{-1} A
__device__ float g_L  [(size_t)BATCH * MDIM * MDIM];   // 64 MB  : G, then L (lower)
__device__ float g_Ldi[(size_t)BATCH * 4 * 64 * 64];   // 4 MB   : inv of diag 64x64 blocks of L
__device__ float g_c  [(size_t)BATCH * MDIM];          // L^{-1} b

// ======================= K1: G = A A^T + jitter*I (3 lower 128x128 tiles) =======================
// 256 threads = 16x16, 8x8 outputs per thread, k-tile 16, double-buffered SMEM (1 sync/tile).
__global__ __launch_bounds__(256, 2) void syrk_kernel(const float* __restrict__ A)
{
    __shared__ float As[2][16][132];
    __shared__ float Bs[2][16][132];
    int t = blockIdx.x, b = blockIdx.y;
    int ti = (t == 0) ? 0 : 1;
    int tj = (t == 2) ? 1 : 0;

    const float* Abase = A + (size_t)b * (MDIM * VDIM);
    const float* Ai = Abase + (size_t)(ti * 128) * VDIM;
    const float* Aj = Abase + (size_t)(tj * 128) * VDIM;

    int tid = threadIdx.x;
    int tx = tid & 15, ty = tid >> 4;
    int lrow = tid >> 2, lf = tid & 3;      // loader: rows lrow & lrow+64, k-offset 4*lf

    float acc[8][8];
#pragma unroll
    for (int i = 0; i < 8; i++)
#pragma unroll
        for (int j = 0; j < 8; j++) acc[i][j] = 0.f;

    // prologue: tile 0 (A is single-use here -> streaming loads, keep L2 clean)
    float4 pa0 = __ldcs((const float4*)&Ai[(size_t)lrow * VDIM + 4 * lf]);
    float4 pa1 = __ldcs((const float4*)&Ai[(size_t)(lrow + 64) * VDIM + 4 * lf]);
    float4 pb0 = __ldcs((const float4*)&Aj[(size_t)lrow * VDIM + 4 * lf]);
    float4 pb1 = __ldcs((const float4*)&Aj[(size_t)(lrow + 64) * VDIM + 4 * lf]);
    {
        float va[4] = {pa0.x, pa0.y, pa0.z, pa0.w};
        float vb[4] = {pa1.x, pa1.y, pa1.z, pa1.w};
        float vc[4] = {pb0.x, pb0.y, pb0.z, pb0.w};
        float vd[4] = {pb1.x, pb1.y, pb1.z, pb1.w};
#pragma unroll
        for (int c = 0; c < 4; c++) {
            As[0][4 * lf + c][lrow]      = va[c];
            As[0][4 * lf + c][lrow + 64] = vb[c];
            Bs[0][4 * lf + c][lrow]      = vc[c];
            Bs[0][4 * lf + c][lrow + 64] = vd[c];
        }
    }
    __syncthreads();

    int buf = 0;
    for (int kt = 0; kt < 64; kt++) {
        if (kt < 63) {
            int k0 = (kt + 1) * 16;
            pa0 = __ldcs((const float4*)&Ai[(size_t)lrow * VDIM + k0 + 4 * lf]);
            pa1 = __ldcs((const float4*)&Ai[(size_t)(lrow + 64) * VDIM + k0 + 4 * lf]);
            pb0 = __ldcs((const float4*)&Aj[(size_t)lrow * VDIM + k0 + 4 * lf]);
            pb1 = __ldcs((const float4*)&Aj[(size_t)(lrow + 64) * VDIM + k0 + 4 * lf]);
        }
#pragma unroll
        for (int kk = 0; kk < 16; kk++) {
            float4 alo = *(const float4*)&As[buf][kk][4 * ty];
            float4 ahi = *(const float4*)&As[buf][kk][64 + 4 * ty];
            float4 blo = *(const float4*)&Bs[buf][kk][4 * tx];
            float4 bhi = *(const float4*)&Bs[buf][kk][64 + 4 * tx];
            float ar[8] = {alo.x, alo.y, alo.z, alo.w, ahi.x, ahi.y, ahi.z, ahi.w};
            float br[8] = {blo.x, blo.y, blo.z, blo.w, bhi.x, bhi.y, bhi.z, bhi.w};
#pragma unroll
            for (int i = 0; i < 8; i++)
#pragma unroll
                for (int j = 0; j < 8; j++) acc[i][j] = fmaf(ar[i], br[j], acc[i][j]);
        }
        if (kt < 63) {
            int nb = buf ^ 1;
            float va[4] = {pa0.x, pa0.y, pa0.z, pa0.w};
            float vb[4] = {pa1.x, pa1.y, pa1.z, pa1.w};
            float vc[4] = {pb0.x, pb0.y, pb0.z, pb0.w};
            float vd[4] = {pb1.x, pb1.y, pb1.z, pb1.w};
#pragma unroll
            for (int c = 0; c < 4; c++) {
                As[nb][4 * lf + c][lrow]      = va[c];
                As[nb][4 * lf + c][lrow + 64] = vb[c];
                Bs[nb][4 * lf + c][lrow]      = vc[c];
                Bs[nb][4 * lf + c][lrow + 64] = vd[c];
            }
            __syncthreads();
            buf = nb;
        }
    }

    float* Gb = g_L + (size_t)b * (MDIM * MDIM);
#pragma unroll
    for (int rr = 0; rr < 8; rr++) {
        int rloc = (rr < 4) ? (4 * ty + rr) : (64 + 4 * ty + rr - 4);
        int grow = ti * 128 + rloc;
#pragma unroll
        for (int q = 0; q < 2; q++) {
            int cloc = 4 * tx + 64 * q;
            float4 v = make_float4(acc[rr][4 * q + 0], acc[rr][4 * q + 1],
                                   acc[rr][4 * q + 2], acc[rr][4 * q + 3]);
            if (ti == tj) {
                int d = rloc - cloc;
                if (d >= 0 && d < 4) ((float*)&v)[d] += JITTER;
            }
            *(float4*)&Gb[(size_t)grow * MDIM + tj * 128 + cloc] = v;
        }
    }
}

// ====== K2: per-batch Cholesky in packed SMEM + diag-block inverses + c = L^{-1} b ======
#define PIDX(i, j) ((i) * ((i) + 1) / 2 + (j))
// smem floats: P 32896 | Inv 16640 | tst 64 | cvec 256 | colk 256 -> 50112 floats
__global__ __launch_bounds__(256) void chol_kernel(const float* __restrict__ b_in)
{
    extern __shared__ float sm2[];
    float* P    = sm2;
    float* Inv  = sm2 + 32896;
    float* tst  = Inv + 4 * 64 * 65;
    float* cvec = tst + 64;
    float* colk = cvec + 256;

    int b = blockIdx.x, tid = threadIdx.x;
    int w = tid >> 5, lane = tid & 31;
    const float* Gb = g_L + (size_t)b * (MDIM * MDIM);

    { // load lower triangle, one row per thread
        int i = tid, base = PIDX(i, 0);
        for (int j = 0; j <= i; j++) P[base + j] = Gb[i * MDIM + j];
    }
    __syncthreads();

    for (int k = 0; k < MDIM; k++) {
        if (tid == 0) P[PIDX(k, k)] = sqrtf(P[PIDX(k, k)]);
        __syncthreads();
        float dk = P[PIDX(k, k)];
        if (tid > k) {
            float v = P[PIDX(tid, 0) + k] / dk;
            P[PIDX(tid, 0) + k] = v;
            colk[tid] = v;
        }
        __syncthreads();
        // rank-1 update: warp-per-row, lanes coalesced over j
        for (int i = k + 1 + w; i < MDIM; i += 8) {
            float lik = colk[i];
            int base = PIDX(i, 0);
            for (int j = k + 1 + lane; j <= i; j += 32)
                P[base + j] = fmaf(-lik, colk[j], P[base + j]);
        }
        __syncthreads();
    }

    { // invert the four 64x64 lower-triangular diagonal blocks (thread = (block,col))
        int blk = tid >> 6, col = tid & 63, b0 = blk * 64;
        float* Ib = Inv + blk * 64 * 65;
        for (int i = 0; i < col; i++) Ib[i * 65 + col] = 0.f;
        for (int i = col; i < 64; i++) {
            int gi = b0 + i, gbase = PIDX(gi, 0);
            float s = (i == col) ? 1.f : 0.f;
            for (int k = col; k < i; k++) s = fmaf(-P[gbase + b0 + k], Ib[k * 65 + col], s);
            Ib[i * 65 + col] = s / P[gbase + gi];
        }
    }
    __syncthreads();

    { // c = L^{-1} b  (blocked forward substitution using the inverses)
        const float* bv = b_in + (size_t)b * MDIM;
        for (int blk = 0; blk < 4; blk++) {
            if (tid < 64) {
                int gi = blk * 64 + tid, gb = PIDX(gi, 0);
                float s = bv[gi];
                for (int j = 0; j < blk * 64; j++) s = fmaf(-P[gb + j], cvec[j], s);
                tst[tid] = s;
            }
            __syncthreads();
            if (tid < 64) {
                const float* Ib = Inv + blk * 64 * 65 + tid * 65;
                float s = 0.f;
                for (int k = 0; k < 64; k++) s = fmaf(Ib[k], tst[k], s);
                cvec[blk * 64 + tid] = s;
            }
            __syncthreads();
        }
    }

    { // write back L (lower), diag-block inverses, c
        int i = tid, base = PIDX(i, 0);
        float* Lo = g_L + (size_t)b * (MDIM * MDIM) + i * MDIM;
        for (int j = 0; j <= i; j++) Lo[j] = P[base + j];

        int blk = tid >> 6, r = tid & 63;
        const float* Ib = Inv + blk * 64 * 65 + r * 65;
        float* o = g_Ldi + (((size_t)b * 4 + blk) * 64 + r) * 64;
        for (int k = 0; k < 64; k++) o[k] = Ib[k];

        g_c[(size_t)b * MDIM + tid] = cvec[tid];
    }
}

// =================== K3: W = L^{-1} A  (blocked trsm; W panel read from global) ===================
// smem floats: Tp 64*132=8448 | { LbT 2*16*68=2176 + Wt 2*16*132=4224 } union { DbT 64*68=4352 }
// total = 8448 + 6400 = 14848 floats = 59392 B  -> 3 CTAs/SM
__global__ __launch_bounds__(256, 2) void trsm_kernel(const float* __restrict__ A)
{
    extern __shared__ float sm3[];
    float* Tp = sm3;             // [64][132]
    float* Lb = sm3 + 8448;      // [2][16][68]
    float* Wt = Lb + 2176;       // [2][16][132]
    float* Db = sm3 + 8448;      // [64][68]  (overlaps Lb/Wt)

    int vt = blockIdx.x, b = blockIdx.y;
    int vc = vt * 128;
    int tid = threadIdx.x, tx = tid & 15, ty = tid >> 4;
    const float* Ab = A + (size_t)b * (MDIM * VDIM);
    const float* Lg = g_L + (size_t)b * (MDIM * MDIM);
    float* Wg = g_W + (size_t)b * (MDIM * VDIM);

    int r4 = tid >> 2, f4 = tid & 3;       // L / Dinv loader
    int kkA = tid >> 5, cg = tid & 31;     // W loader (kkA and kkA+8)

    for (int i = 0; i < 4; i++) {
        float acc[4][8];
#pragma unroll
        for (int r = 0; r < 4; r++)
#pragma unroll
            for (int q = 0; q < 2; q++) {
                float4 av = __ldcs((const float4*)&Ab[(size_t)(i * 64 + 4 * ty + r) * VDIM + vc + 4 * tx + 64 * q]);
                acc[r][4 * q + 0] = av.x; acc[r][4 * q + 1] = av.y;
                acc[r][4 * q + 2] = av.z; acc[r][4 * q + 3] = av.w;
            }

        int nkt = 4 * i;   // k-extent = 64*i, tiles of 16
        if (nkt > 0) {
            // prologue k0 = 0
            float4 lv  = *(const float4*)&Lg[(size_t)(i * 64 + r4) * MDIM + 4 * f4];
            float4 wv0 = *(const float4*)&Wg[(size_t)(kkA)     * VDIM + vc + 4 * cg];
            float4 wv1 = *(const float4*)&Wg[(size_t)(kkA + 8) * VDIM + vc + 4 * cg];
            Lb[(4 * f4 + 0) * 68 + r4] = lv.x; Lb[(4 * f4 + 1) * 68 + r4] = lv.y;
            Lb[(4 * f4 + 2) * 68 + r4] = lv.z; Lb[(4 * f4 + 3) * 68 + r4] = lv.w;
            *(float4*)&Wt[kkA * 132 + 4 * cg] = wv0;
            *(float4*)&Wt[(kkA + 8) * 132 + 4 * cg] = wv1;
            __syncthreads();

            int buf = 0;
            for (int kt = 0; kt < nkt; kt++) {
                float4 lvn, wv0n, wv1n;
                if (kt + 1 < nkt) {
                    int k0 = (kt + 1) * 16;
                    lvn  = *(const float4*)&Lg[(size_t)(i * 64 + r4) * MDIM + k0 + 4 * f4];
                    wv0n = *(const float4*)&Wg[(size_t)(k0 + kkA)     * VDIM + vc + 4 * cg];
                    wv1n = *(const float4*)&Wg[(size_t)(k0 + kkA + 8) * VDIM + vc + 4 * cg];
                }
                const float* Lc = Lb + buf * 1088;
                const float* Wc = Wt + buf * 2112;
#pragma unroll
                for (int kk = 0; kk < 16; kk++) {
                    float4 a4 = *(const float4*)&Lc[kk * 68 + 4 * ty];
                    float4 w0 = *(const float4*)&Wc[kk * 132 + 4 * tx];
                    float4 w1 = *(const float4*)&Wc[kk * 132 + 64 + 4 * tx];
                    float ar[4] = {a4.x, a4.y, a4.z, a4.w};
                    float wv[8] = {w0.x, w0.y, w0.z, w0.w, w1.x, w1.y, w1.z, w1.w};
#pragma unroll
                    for (int r = 0; r < 4; r++)
#pragma unroll
                        for (int c = 0; c < 8; c++) acc[r][c] = fmaf(-ar[r], wv[c], acc[r][c]);
                }
                if (kt + 1 < nkt) {
                    int nb = buf ^ 1;
                    float* Ln = Lb + nb * 1088;
                    float* Wn = Wt + nb * 2112;
                    Ln[(4 * f4 + 0) * 68 + r4] = lvn.x; Ln[(4 * f4 + 1) * 68 + r4] = lvn.y;
                    Ln[(4 * f4 + 2) * 68 + r4] = lvn.z; Ln[(4 * f4 + 3) * 68 + r4] = lvn.w;
                    *(float4*)&Wn[kkA * 132 + 4 * cg] = wv0n;
                    *(float4*)&Wn[(kkA + 8) * 132 + 4 * cg] = wv1n;
                    __syncthreads();
                    buf = nb;
                }
            }
            __syncthreads();   // all GEMM smem reads done before Db overwrite
        }

        // stage acc -> Tp
#pragma unroll
        for (int r = 0; r < 4; r++)
#pragma unroll
            for (int q = 0; q < 2; q++) {
                float4 o = make_float4(acc[r][4 * q + 0], acc[r][4 * q + 1],
                                       acc[r][4 * q + 2], acc[r][4 * q + 3]);
                *(float4*)&Tp[(4 * ty + r) * 132 + 4 * tx + 64 * q] = o;
            }
        // load Dinv_i transposed into Db: Db[k][r] = Dinv[r][k]
#pragma unroll
        for (int s = 0; s < 4; s++) {
            int n = tid + 256 * s;
            int r = n >> 4, f = n & 15;
            float4 dv = *(const float4*)&g_Ldi[(((size_t)b * 4 + i) * 64 + r) * 64 + 4 * f];
            Db[(4 * f + 0) * 68 + r] = dv.x; Db[(4 * f + 1) * 68 + r] = dv.y;
            Db[(4 * f + 2) * 68 + r] = dv.z; Db[(4 * f + 3) * 68 + r] = dv.w;
        }
        __syncthreads();

        float acc2[4][8];
#pragma unroll
        for (int r = 0; r < 4; r++)
#pragma unroll
            for (int c = 0; c < 8; c++) acc2[r][c] = 0.f;
#pragma unroll 16
        for (int kk = 0; kk < 64; kk++) {
            float4 a4 = *(const float4*)&Db[kk * 68 + 4 * ty];
            float4 t0 = *(const float4*)&Tp[kk * 132 + 4 * tx];
            float4 t1 = *(const float4*)&Tp[kk * 132 + 64 + 4 * tx];
            float ar[4] = {a4.x, a4.y, a4.z, a4.w};
            float tv[8] = {t0.x, t0.y, t0.z, t0.w, t1.x, t1.y, t1.z, t1.w};
#pragma unroll
            for (int r = 0; r < 4; r++)
#pragma unroll
                for (int c = 0; c < 8; c++) acc2[r][c] = fmaf(ar[r], tv[c], acc2[r][c]);
        }

#pragma unroll
        for (int r = 0; r < 4; r++)
#pragma unroll
            for (int q = 0; q < 2; q++) {
                float4 o = make_float4(acc2[r][4 * q + 0], acc2[r][4 * q + 1],
                                       acc2[r][4 * q + 2], acc2[r][4 * q + 3]);
                *(float4*)&Wg[(size_t)(i * 64 + 4 * ty + r) * VDIM + vc + 4 * tx + 64 * q] = o;
            }
        __syncthreads();   // W rows visible to this CTA; Tp/Db reads complete
    }
}

// =================== K5: fused ADMM loop (persistent CTA per batch, d folded in) ===================
// xk = 0.5*r - sum_m (0.5*s_m - c_m) w_m,   s_m = w_m . r
// W rows 0..(32*CACHED_WARPS-1): default (evict-normal) loads -> stay L2-resident (96 MB).
// W rows 96..255: __ldcs (evict-first) -> stream through L2 without evicting the resident set.
// smem floats: rsh 1024 | vp 8*1024 | cc 256 -> 9472 floats = 37888 B
__global__ __launch_bounds__(256, 2) void admm_kernel(
    const float* __restrict__ x_in, const int* __restrict__ mask,
    float* __restrict__ out)
{
    extern __shared__ float sm5[];
    float* rsh = sm5;          // 1024
    float* vp  = sm5 + 1024;   // 8*1024
    float* cc  = sm5 + 9216;   // 256

    int b = blockIdx.x, tid = threadIdx.x;
    int w = tid >> 5, lane = tid & 31;
    const float* Wb = g_W + (size_t)b * (MDIM * VDIM);

    float4 xreg = *(const float4*)&x_in[(size_t)b * VDIM + 4 * tid];
    int4 m4 = *(const int4*)&mask[4 * tid];
    float4 ureg = make_float4(0.f, 0.f, 0.f, 0.f);
    float4 rown = xreg;   // this thread's own 4 entries of r
    cc[tid] = g_c[(size_t)b * MDIM + tid];
    *(float4*)&rsh[4 * tid] = xreg;

    bool cached = (w < CACHED_WARPS);

    for (int it = 0; it <= 100; it++) {
        __syncthreads();   // r in SMEM ready; vp free for reuse
        float4 rr[8];
#pragma unroll
        for (int q = 0; q < 8; q++) rr[q] = *(float4*)&rsh[q * 128 + 4 * lane];
        float4 v[8];
#pragma unroll
        for (int q = 0; q < 8; q++) v[q] = make_float4(0.f, 0.f, 0.f, 0.f);

        for (int j = 0; j < 32; j++) {
            int m = (w << 5) + j;
            const float4* row = (const float4*)(Wb + (size_t)m * VDIM);
            float4 a[8];
            if (cached) {
#pragma unroll
                for (int q = 0; q < 8; q++) a[q] = row[lane + 32 * q];
            } else {
#pragma unroll
                for (int q = 0; q < 8; q++) a[q] = __ldcs(&row[lane + 32 * q]);
            }
            float s = 0.f;
#pragma unroll
            for (int q = 0; q < 8; q++) {
                s = fmaf(a[q].x, rr[q].x, s); s = fmaf(a[q].y, rr[q].y, s);
                s = fmaf(a[q].z, rr[q].z, s); s = fmaf(a[q].w, rr[q].w, s);
            }
#pragma unroll
            for (int off = 16; off > 0; off >>= 1) s += __shfl_xor_sync(0xffffffffu, s, off);
            float coef = 0.5f * s - cc[m];
#pragma unroll
            for (int q = 0; q < 8; q++) {
                v[q].x = fmaf(coef, a[q].x, v[q].x); v[q].y = fmaf(coef, a[q].y, v[q].y);
                v[q].z = fmaf(coef, a[q].z, v[q].z); v[q].w = fmaf(coef, a[q].w, v[q].w);
            }
        }
#pragma unroll
        for (int q = 0; q < 8; q++) *(float4*)&vp[w * 1024 + q * 128 + 4 * lane] = v[q];
        __syncthreads();

        float4 vs = make_float4(0.f, 0.f, 0.f, 0.f);
#pragma unroll
        for (int ww = 0; ww < 8; ww++) {
            float4 p = *(float4*)&vp[ww * 1024 + 4 * tid];
            vs.x += p.x; vs.y += p.y; vs.z += p.z; vs.w += p.w;
        }
        float4 xk;
        xk.x = 0.5f * rown.x - vs.x;
        xk.y = 0.5f * rown.y - vs.y;
        xk.z = 0.5f * rown.z - vs.z;
        xk.w = 0.5f * rown.w - vs.w;

        if (it == 100) {
            *(float4*)&out[(size_t)b * VDIM + 4 * tid] = xk;
        } else {
            float wv, zv;
            wv = xk.x + ureg.x; zv = (m4.x > 0) ? fminf(wv, 0.f) : wv; ureg.x = wv - zv; rown.x = xreg.x + zv - ureg.x;
            wv = xk.y + ureg.y; zv = (m4.y > 0) ? fminf(wv, 0.f) : wv; ureg.y = wv - zv; rown.y = xreg.y + zv - ureg.y;
            wv = xk.z + ureg.z; zv = (m4.z > 0) ? fminf(wv, 0.f) : wv; ureg.z = wv - zv; rown.z = xreg.z + zv - ureg.z;
            wv = xk.w + ureg.w; zv = (m4.w > 0) ? fminf(wv, 0.f) : wv; ureg.w = wv - zv; rown.w = xreg.w + zv - ureg.w;
            *(float4*)&rsh[4 * tid] = rown;
        }
    }
}

// ======================================= launch =======================================
extern "C" void kernel_launch(void* const* d_in, const int* in_sizes, int n_in,
                              void* d_out, int out_size)
{
    (void)in_sizes; (void)n_in; (void)out_size;
    const float* x    = (const float*)d_in[0];
    const float* bvec = (const float*)d_in[1];
    const float* A    = (const float*)d_in[2];
    const int*   mask = (const int*)d_in[3];
    float* out = (float*)d_out;

    size_t chol_smem = (size_t)(32896 + 4 * 64 * 65 + 64 + 256 + 256) * sizeof(float); // 200448 B
    size_t trsm_smem = (size_t)(8448 + 2176 + 4224) * sizeof(float);                   // 59392 B
    size_t admm_smem = (size_t)(1024 + 8 * 1024 + 256) * sizeof(float);                // 37888 B

    cudaFuncSetAttribute((const void*)chol_kernel, cudaFuncAttributeMaxDynamicSharedMemorySize, (int)chol_smem);
    cudaFuncSetAttribute((const void*)trsm_kernel, cudaFuncAttributeMaxDynamicSharedMemorySize, (int)trsm_smem);

    syrk_kernel<<<dim3(3, BATCH), 256>>>(A);
    chol_kernel<<<BATCH, 256, chol_smem>>>(bvec);
    trsm_kernel<<<dim3(8, BATCH), 256, trsm_smem>>>(A);
    admm_kernel<<<BATCH, 256, admm_smem>>>(x, mask, out);
}

// round 5
// speedup vs baseline: 1.3093x; 1.1553x over previous
#include <cuda_runtime.h>
#include <cuda_fp16.h>
#include <math.h>

#define BATCH 256
#define MDIM  256
#define VDIM  1024
#define JITTER 1e-6f
#define CACHED_WARPS 6   // warps 0..5 -> W rows 0..191 (96 MB fp16 chip-wide) kept L2-resident

// ------------------------- device scratch (no allocs allowed) -------------------------
__device__ float  g_W  [(size_t)BATCH * MDIM * VDIM];   // 256 MB : W = L^{-1} A (fp32)
__device__ __half g_Wh [(size_t)BATCH * MDIM * VDIM];   // 128 MB : W in fp16 (iteration copy)
__device__ float  g_L  [(size_t)BATCH * MDIM * MDIM];   // 64 MB  : G, then L (lower)
__device__ float  g_Ldi[(size_t)BATCH * 4 * 64 * 64];   // 4 MB   : inv of diag 64x64 blocks of L
__device__ float  g_c  [(size_t)BATCH * MDIM];          // L^{-1} b

// ======================= K1: G = A A^T + jitter*I (3 lower 128x128 tiles) =======================
__global__ __launch_bounds__(256, 2) void syrk_kernel(const float* __restrict__ A)
{
    __shared__ float As[2][16][132];
    __shared__ float Bs[2][16][132];
    int t = blockIdx.x, b = blockIdx.y;
    int ti = (t == 0) ? 0 : 1;
    int tj = (t == 2) ? 1 : 0;

    const float* Abase = A + (size_t)b * (MDIM * VDIM);
    const float* Ai = Abase + (size_t)(ti * 128) * VDIM;
    const float* Aj = Abase + (size_t)(tj * 128) * VDIM;

    int tid = threadIdx.x;
    int tx = tid & 15, ty = tid >> 4;
    int lrow = tid >> 2, lf = tid & 3;

    float acc[8][8];
#pragma unroll
    for (int i = 0; i < 8; i++)
#pragma unroll
        for (int j = 0; j < 8; j++) acc[i][j] = 0.f;

    float4 pa0 = __ldcs((const float4*)&Ai[(size_t)lrow * VDIM + 4 * lf]);
    float4 pa1 = __ldcs((const float4*)&Ai[(size_t)(lrow + 64) * VDIM + 4 * lf]);
    float4 pb0 = __ldcs((const float4*)&Aj[(size_t)lrow * VDIM + 4 * lf]);
    float4 pb1 = __ldcs((const float4*)&Aj[(size_t)(lrow + 64) * VDIM + 4 * lf]);
    {
        float va[4] = {pa0.x, pa0.y, pa0.z, pa0.w};
        float vb[4] = {pa1.x, pa1.y, pa1.z, pa1.w};
        float vc[4] = {pb0.x, pb0.y, pb0.z, pb0.w};
        float vd[4] = {pb1.x, pb1.y, pb1.z, pb1.w};
#pragma unroll
        for (int c = 0; c < 4; c++) {
            As[0][4 * lf + c][lrow]      = va[c];
            As[0][4 * lf + c][lrow + 64] = vb[c];
            Bs[0][4 * lf + c][lrow]      = vc[c];
            Bs[0][4 * lf + c][lrow + 64] = vd[c];
        }
    }
    __syncthreads();

    int buf = 0;
    for (int kt = 0; kt < 64; kt++) {
        if (kt < 63) {
            int k0 = (kt + 1) * 16;
            pa0 = __ldcs((const float4*)&Ai[(size_t)lrow * VDIM + k0 + 4 * lf]);
            pa1 = __ldcs((const float4*)&Ai[(size_t)(lrow + 64) * VDIM + k0 + 4 * lf]);
            pb0 = __ldcs((const float4*)&Aj[(size_t)lrow * VDIM + k0 + 4 * lf]);
            pb1 = __ldcs((const float4*)&Aj[(size_t)(lrow + 64) * VDIM + k0 + 4 * lf]);
        }
#pragma unroll
        for (int kk = 0; kk < 16; kk++) {
            float4 alo = *(const float4*)&As[buf][kk][4 * ty];
            float4 ahi = *(const float4*)&As[buf][kk][64 + 4 * ty];
            float4 blo = *(const float4*)&Bs[buf][kk][4 * tx];
            float4 bhi = *(const float4*)&Bs[buf][kk][64 + 4 * tx];
            float ar[8] = {alo.x, alo.y, alo.z, alo.w, ahi.x, ahi.y, ahi.z, ahi.w};
            float br[8] = {blo.x, blo.y, blo.z, blo.w, bhi.x, bhi.y, bhi.z, bhi.w};
#pragma unroll
            for (int i = 0; i < 8; i++)
#pragma unroll
                for (int j = 0; j < 8; j++) acc[i][j] = fmaf(ar[i], br[j], acc[i][j]);
        }
        if (kt < 63) {
            int nb = buf ^ 1;
            float va[4] = {pa0.x, pa0.y, pa0.z, pa0.w};
            float vb[4] = {pa1.x, pa1.y, pa1.z, pa1.w};
            float vc[4] = {pb0.x, pb0.y, pb0.z, pb0.w};
            float vd[4] = {pb1.x, pb1.y, pb1.z, pb1.w};
#pragma unroll
            for (int c = 0; c < 4; c++) {
                As[nb][4 * lf + c][lrow]      = va[c];
                As[nb][4 * lf + c][lrow + 64] = vb[c];
                Bs[nb][4 * lf + c][lrow]      = vc[c];
                Bs[nb][4 * lf + c][lrow + 64] = vd[c];
            }
            __syncthreads();
            buf = nb;
        }
    }

    float* Gb = g_L + (size_t)b * (MDIM * MDIM);
#pragma unroll
    for (int rr = 0; rr < 8; rr++) {
        int rloc = (rr < 4) ? (4 * ty + rr) : (64 + 4 * ty + rr - 4);
        int grow = ti * 128 + rloc;
#pragma unroll
        for (int q = 0; q < 2; q++) {
            int cloc = 4 * tx + 64 * q;
            float4 v = make_float4(acc[rr][4 * q + 0], acc[rr][4 * q + 1],
                                   acc[rr][4 * q + 2], acc[rr][4 * q + 3]);
            if (ti == tj) {
                int d = rloc - cloc;
                if (d >= 0 && d < 4) ((float*)&v)[d] += JITTER;
            }
            *(float4*)&Gb[(size_t)grow * MDIM + tj * 128 + cloc] = v;
        }
    }
}

// ====== K2: per-batch Cholesky in packed SMEM + diag-block inverses + c = L^{-1} b ======
#define PIDX(i, j) ((i) * ((i) + 1) / 2 + (j))
__global__ __launch_bounds__(256) void chol_kernel(const float* __restrict__ b_in)
{
    extern __shared__ float sm2[];
    float* P    = sm2;
    float* Inv  = sm2 + 32896;
    float* tst  = Inv + 4 * 64 * 65;
    float* cvec = tst + 64;
    float* colk = cvec + 256;

    int b = blockIdx.x, tid = threadIdx.x;
    int w = tid >> 5, lane = tid & 31;
    const float* Gb = g_L + (size_t)b * (MDIM * MDIM);

    {
        int i = tid, base = PIDX(i, 0);
        for (int j = 0; j <= i; j++) P[base + j] = Gb[i * MDIM + j];
    }
    __syncthreads();

    for (int k = 0; k < MDIM; k++) {
        if (tid == 0) P[PIDX(k, k)] = sqrtf(P[PIDX(k, k)]);
        __syncthreads();
        float dk = P[PIDX(k, k)];
        if (tid > k) {
            float v = P[PIDX(tid, 0) + k] / dk;
            P[PIDX(tid, 0) + k] = v;
            colk[tid] = v;
        }
        __syncthreads();
        for (int i = k + 1 + w; i < MDIM; i += 8) {
            float lik = colk[i];
            int base = PIDX(i, 0);
            for (int j = k + 1 + lane; j <= i; j += 32)
                P[base + j] = fmaf(-lik, colk[j], P[base + j]);
        }
        __syncthreads();
    }

    {
        int blk = tid >> 6, col = tid & 63, b0 = blk * 64;
        float* Ib = Inv + blk * 64 * 65;
        for (int i = 0; i < col; i++) Ib[i * 65 + col] = 0.f;
        for (int i = col; i < 64; i++) {
            int gi = b0 + i, gbase = PIDX(gi, 0);
            float s = (i == col) ? 1.f : 0.f;
            for (int k = col; k < i; k++) s = fmaf(-P[gbase + b0 + k], Ib[k * 65 + col], s);
            Ib[i * 65 + col] = s / P[gbase + gi];
        }
    }
    __syncthreads();

    {
        const float* bv = b_in + (size_t)b * MDIM;
        for (int blk = 0; blk < 4; blk++) {
            if (tid < 64) {
                int gi = blk * 64 + tid, gb = PIDX(gi, 0);
                float s = bv[gi];
                for (int j = 0; j < blk * 64; j++) s = fmaf(-P[gb + j], cvec[j], s);
                tst[tid] = s;
            }
            __syncthreads();
            if (tid < 64) {
                const float* Ib = Inv + blk * 64 * 65 + tid * 65;
                float s = 0.f;
                for (int k = 0; k < 64; k++) s = fmaf(Ib[k], tst[k], s);
                cvec[blk * 64 + tid] = s;
            }
            __syncthreads();
        }
    }

    {
        int i = tid, base = PIDX(i, 0);
        float* Lo = g_L + (size_t)b * (MDIM * MDIM) + i * MDIM;
        for (int j = 0; j <= i; j++) Lo[j] = P[base + j];

        int blk = tid >> 6, r = tid & 63;
        const float* Ib = Inv + blk * 64 * 65 + r * 65;
        float* o = g_Ldi + (((size_t)b * 4 + blk) * 64 + r) * 64;
        for (int k = 0; k < 64; k++) o[k] = Ib[k];

        g_c[(size_t)b * MDIM + tid] = cvec[tid];
    }
}

// =================== K3: W = L^{-1} A  (blocked trsm; writes fp32 + fp16 copies) ===================
__global__ __launch_bounds__(256, 2) void trsm_kernel(const float* __restrict__ A)
{
    extern __shared__ float sm3[];
    float* Tp = sm3;             // [64][132]
    float* Lb = sm3 + 8448;      // [2][16][68]
    float* Wt = Lb + 2176;       // [2][16][132]
    float* Db = sm3 + 8448;      // [64][68]  (overlaps Lb/Wt)

    int vt = blockIdx.x, b = blockIdx.y;
    int vc = vt * 128;
    int tid = threadIdx.x, tx = tid & 15, ty = tid >> 4;
    const float* Ab = A + (size_t)b * (MDIM * VDIM);
    const float* Lg = g_L + (size_t)b * (MDIM * MDIM);
    float* Wg = g_W + (size_t)b * (MDIM * VDIM);
    __half* Wh = g_Wh + (size_t)b * (MDIM * VDIM);

    int r4 = tid >> 2, f4 = tid & 3;
    int kkA = tid >> 5, cg = tid & 31;

    for (int i = 0; i < 4; i++) {
        float acc[4][8];
#pragma unroll
        for (int r = 0; r < 4; r++)
#pragma unroll
            for (int q = 0; q < 2; q++) {
                float4 av = __ldcs((const float4*)&Ab[(size_t)(i * 64 + 4 * ty + r) * VDIM + vc + 4 * tx + 64 * q]);
                acc[r][4 * q + 0] = av.x; acc[r][4 * q + 1] = av.y;
                acc[r][4 * q + 2] = av.z; acc[r][4 * q + 3] = av.w;
            }

        int nkt = 4 * i;
        if (nkt > 0) {
            float4 lv  = *(const float4*)&Lg[(size_t)(i * 64 + r4) * MDIM + 4 * f4];
            float4 wv0 = *(const float4*)&Wg[(size_t)(kkA)     * VDIM + vc + 4 * cg];
            float4 wv1 = *(const float4*)&Wg[(size_t)(kkA + 8) * VDIM + vc + 4 * cg];
            Lb[(4 * f4 + 0) * 68 + r4] = lv.x; Lb[(4 * f4 + 1) * 68 + r4] = lv.y;
            Lb[(4 * f4 + 2) * 68 + r4] = lv.z; Lb[(4 * f4 + 3) * 68 + r4] = lv.w;
            *(float4*)&Wt[kkA * 132 + 4 * cg] = wv0;
            *(float4*)&Wt[(kkA + 8) * 132 + 4 * cg] = wv1;
            __syncthreads();

            int buf = 0;
            for (int kt = 0; kt < nkt; kt++) {
                float4 lvn, wv0n, wv1n;
                if (kt + 1 < nkt) {
                    int k0 = (kt + 1) * 16;
                    lvn  = *(const float4*)&Lg[(size_t)(i * 64 + r4) * MDIM + k0 + 4 * f4];
                    wv0n = *(const float4*)&Wg[(size_t)(k0 + kkA)     * VDIM + vc + 4 * cg];
                    wv1n = *(const float4*)&Wg[(size_t)(k0 + kkA + 8) * VDIM + vc + 4 * cg];
                }
                const float* Lc = Lb + buf * 1088;
                const float* Wc = Wt + buf * 2112;
#pragma unroll
                for (int kk = 0; kk < 16; kk++) {
                    float4 a4 = *(const float4*)&Lc[kk * 68 + 4 * ty];
                    float4 w0 = *(const float4*)&Wc[kk * 132 + 4 * tx];
                    float4 w1 = *(const float4*)&Wc[kk * 132 + 64 + 4 * tx];
                    float ar[4] = {a4.x, a4.y, a4.z, a4.w};
                    float wv[8] = {w0.x, w0.y, w0.z, w0.w, w1.x, w1.y, w1.z, w1.w};
#pragma unroll
                    for (int r = 0; r < 4; r++)
#pragma unroll
                        for (int c = 0; c < 8; c++) acc[r][c] = fmaf(-ar[r], wv[c], acc[r][c]);
                }
                if (kt + 1 < nkt) {
                    int nb = buf ^ 1;
                    float* Ln = Lb + nb * 1088;
                    float* Wn = Wt + nb * 2112;
                    Ln[(4 * f4 + 0) * 68 + r4] = lvn.x; Ln[(4 * f4 + 1) * 68 + r4] = lvn.y;
                    Ln[(4 * f4 + 2) * 68 + r4] = lvn.z; Ln[(4 * f4 + 3) * 68 + r4] = lvn.w;
                    *(float4*)&Wn[kkA * 132 + 4 * cg] = wv0n;
                    *(float4*)&Wn[(kkA + 8) * 132 + 4 * cg] = wv1n;
                    __syncthreads();
                    buf = nb;
                }
            }
            __syncthreads();
        }

#pragma unroll
        for (int r = 0; r < 4; r++)
#pragma unroll
            for (int q = 0; q < 2; q++) {
                float4 o = make_float4(acc[r][4 * q + 0], acc[r][4 * q + 1],
                                       acc[r][4 * q + 2], acc[r][4 * q + 3]);
                *(float4*)&Tp[(4 * ty + r) * 132 + 4 * tx + 64 * q] = o;
            }
#pragma unroll
        for (int s = 0; s < 4; s++) {
            int n = tid + 256 * s;
            int r = n >> 4, f = n & 15;
            float4 dv = *(const float4*)&g_Ldi[(((size_t)b * 4 + i) * 64 + r) * 64 + 4 * f];
            Db[(4 * f + 0) * 68 + r] = dv.x; Db[(4 * f + 1) * 68 + r] = dv.y;
            Db[(4 * f + 2) * 68 + r] = dv.z; Db[(4 * f + 3) * 68 + r] = dv.w;
        }
        __syncthreads();

        float acc2[4][8];
#pragma unroll
        for (int r = 0; r < 4; r++)
#pragma unroll
            for (int c = 0; c < 8; c++) acc2[r][c] = 0.f;
#pragma unroll 16
        for (int kk = 0; kk < 64; kk++) {
            float4 a4 = *(const float4*)&Db[kk * 68 + 4 * ty];
            float4 t0 = *(const float4*)&Tp[kk * 132 + 4 * tx];
            float4 t1 = *(const float4*)&Tp[kk * 132 + 64 + 4 * tx];
            float ar[4] = {a4.x, a4.y, a4.z, a4.w};
            float tv[8] = {t0.x, t0.y, t0.z, t0.w, t1.x, t1.y, t1.z, t1.w};
#pragma unroll
            for (int r = 0; r < 4; r++)
#pragma unroll
                for (int c = 0; c < 8; c++) acc2[r][c] = fmaf(ar[r], tv[c], acc2[r][c]);
        }

#pragma unroll
        for (int r = 0; r < 4; r++)
#pragma unroll
            for (int q = 0; q < 2; q++) {
                float4 o = make_float4(acc2[r][4 * q + 0], acc2[r][4 * q + 1],
                                       acc2[r][4 * q + 2], acc2[r][4 * q + 3]);
                size_t off = (size_t)(i * 64 + 4 * ty + r) * VDIM + vc + 4 * tx + 64 * q;
                *(float4*)&Wg[off] = o;
                __half2 h01 = __floats2half2_rn(o.x, o.y);
                __half2 h23 = __floats2half2_rn(o.z, o.w);
                __half2 hh[2] = {h01, h23};
                *(uint2*)&Wh[off] = *(uint2*)hh;
            }
        __syncthreads();
    }
}

// =================== K5: fused ADMM loop (fp16 W iterations, fp32 W final pass) ===================
// xk = 0.5*r - sum_m (0.5*s_m - c_m) w_m,   s_m = w_m . r
// smem floats: rsh 1024 | vp 8*1024 | cc 256 -> 9472 floats = 37888 B
__global__ __launch_bounds__(256, 2) void admm_kernel(
    const float* __restrict__ x_in, const int* __restrict__ mask,
    float* __restrict__ out)
{
    extern __shared__ float sm5[];
    float* rsh = sm5;          // 1024
    float* vp  = sm5 + 1024;   // 8*1024
    float* cc  = sm5 + 9216;   // 256

    int b = blockIdx.x, tid = threadIdx.x;
    int w = tid >> 5, lane = tid & 31;
    const __half* Whb = g_Wh + (size_t)b * (MDIM * VDIM);
    const float*  Wfb = g_W  + (size_t)b * (MDIM * VDIM);

    float4 xreg = *(const float4*)&x_in[(size_t)b * VDIM + 4 * tid];
    int4 m4 = *(const int4*)&mask[4 * tid];
    float4 ureg = make_float4(0.f, 0.f, 0.f, 0.f);
    float4 rown = xreg;   // this thread's own 4 entries of r (cols 4*tid..4*tid+3)
    cc[tid] = g_c[(size_t)b * MDIM + tid];
    *(float4*)&rsh[4 * tid] = xreg;

    bool cached = (w < CACHED_WARPS);

    for (int it = 0; it <= 100; it++) {
        __syncthreads();   // r in SMEM ready; vp free for reuse
        // this lane's 32 r-values: cols 256*q + 8*lane + c  (q=0..3, c=0..7)
        float rr[32];
#pragma unroll
        for (int q = 0; q < 4; q++) {
            float4 r0 = *(float4*)&rsh[256 * q + 8 * lane];
            float4 r1 = *(float4*)&rsh[256 * q + 8 * lane + 4];
            rr[8 * q + 0] = r0.x; rr[8 * q + 1] = r0.y; rr[8 * q + 2] = r0.z; rr[8 * q + 3] = r0.w;
            rr[8 * q + 4] = r1.x; rr[8 * q + 5] = r1.y; rr[8 * q + 6] = r1.z; rr[8 * q + 7] = r1.w;
        }
        float v[32];
#pragma unroll
        for (int c = 0; c < 32; c++) v[c] = 0.f;

        for (int j = 0; j < 32; j++) {
            int m = (w << 5) + j;
            float af[32];
            if (it < 100) {
                const uint4* row = (const uint4*)(Whb + (size_t)m * VDIM);
#pragma unroll
                for (int q = 0; q < 4; q++) {
                    uint4 u = cached ? row[lane + 32 * q] : __ldcs(&row[lane + 32 * q]);
                    float2 f0 = __half22float2(*(__half2*)&u.x);
                    float2 f1 = __half22float2(*(__half2*)&u.y);
                    float2 f2 = __half22float2(*(__half2*)&u.z);
                    float2 f3 = __half22float2(*(__half2*)&u.w);
                    af[8 * q + 0] = f0.x; af[8 * q + 1] = f0.y;
                    af[8 * q + 2] = f1.x; af[8 * q + 3] = f1.y;
                    af[8 * q + 4] = f2.x; af[8 * q + 5] = f2.y;
                    af[8 * q + 6] = f3.x; af[8 * q + 7] = f3.y;
                }
            } else {
                // final pass: exact fp32 W (cold in L2; pure stream)
                const float4* row = (const float4*)(Wfb + (size_t)m * VDIM);
#pragma unroll
                for (int q = 0; q < 4; q++) {
                    float4 a0 = __ldcs(&row[2 * (lane + 32 * q)]);
                    float4 a1 = __ldcs(&row[2 * (lane + 32 * q) + 1]);
                    af[8 * q + 0] = a0.x; af[8 * q + 1] = a0.y; af[8 * q + 2] = a0.z; af[8 * q + 3] = a0.w;
                    af[8 * q + 4] = a1.x; af[8 * q + 5] = a1.y; af[8 * q + 6] = a1.z; af[8 * q + 7] = a1.w;
                }
            }
            float s = 0.f;
#pragma unroll
            for (int c = 0; c < 32; c++) s = fmaf(af[c], rr[c], s);
#pragma unroll
            for (int off = 16; off > 0; off >>= 1) s += __shfl_xor_sync(0xffffffffu, s, off);
            float coef = 0.5f * s - cc[m];
#pragma unroll
            for (int c = 0; c < 32; c++) v[c] = fmaf(coef, af[c], v[c]);
        }
        // partials to SMEM: vp[w*1024 + col], col = 256*q + 8*lane + c
#pragma unroll
        for (int q = 0; q < 4; q++) {
            *(float4*)&vp[w * 1024 + 256 * q + 8 * lane]     = make_float4(v[8 * q + 0], v[8 * q + 1], v[8 * q + 2], v[8 * q + 3]);
            *(float4*)&vp[w * 1024 + 256 * q + 8 * lane + 4] = make_float4(v[8 * q + 4], v[8 * q + 5], v[8 * q + 6], v[8 * q + 7]);
        }
        __syncthreads();

        float4 vs = make_float4(0.f, 0.f, 0.f, 0.f);
#pragma unroll
        for (int ww = 0; ww < 8; ww++) {
            float4 p = *(float4*)&vp[ww * 1024 + 4 * tid];
            vs.x += p.x; vs.y += p.y; vs.z += p.z; vs.w += p.w;
        }
        float4 xk;
        xk.x = 0.5f * rown.x - vs.x;
        xk.y = 0.5f * rown.y - vs.y;
        xk.z = 0.5f * rown.z - vs.z;
        xk.w = 0.5f * rown.w - vs.w;

        if (it == 100) {
            *(float4*)&out[(size_t)b * VDIM + 4 * tid] = xk;
        } else {
            float wv, zv;
            wv = xk.x + ureg.x; zv = (m4.x > 0) ? fminf(wv, 0.f) : wv; ureg.x = wv - zv; rown.x = xreg.x + zv - ureg.x;
            wv = xk.y + ureg.y; zv = (m4.y > 0) ? fminf(wv, 0.f) : wv; ureg.y = wv - zv; rown.y = xreg.y + zv - ureg.y;
            wv = xk.z + ureg.z; zv = (m4.z > 0) ? fminf(wv, 0.f) : wv; ureg.z = wv - zv; rown.z = xreg.z + zv - ureg.z;
            wv = xk.w + ureg.w; zv = (m4.w > 0) ? fminf(wv, 0.f) : wv; ureg.w = wv - zv; rown.w = xreg.w + zv - ureg.w;
            *(float4*)&rsh[4 * tid] = rown;
        }
    }
}

// ======================================= launch =======================================
extern "C" void kernel_launch(void* const* d_in, const int* in_sizes, int n_in,
                              void* d_out, int out_size)
{
    (void)in_sizes; (void)n_in; (void)out_size;
    const float* x    = (const float*)d_in[0];
    const float* bvec = (const float*)d_in[1];
    const float* A    = (const float*)d_in[2];
    const int*   mask = (const int*)d_in[3];
    float* out = (float*)d_out;

    size_t chol_smem = (size_t)(32896 + 4 * 64 * 65 + 64 + 256 + 256) * sizeof(float); // 200448 B
    size_t trsm_smem = (size_t)(8448 + 2176 + 4224) * sizeof(float);                   // 59392 B
    size_t admm_smem = (size_t)(1024 + 8 * 1024 + 256) * sizeof(float);                // 37888 B

    cudaFuncSetAttribute((const void*)chol_kernel, cudaFuncAttributeMaxDynamicSharedMemorySize, (int)chol_smem);
    cudaFuncSetAttribute((const void*)trsm_kernel, cudaFuncAttributeMaxDynamicSharedMemorySize, (int)trsm_smem);

    syrk_kernel<<<dim3(3, BATCH), 256>>>(A);
    chol_kernel<<<BATCH, 256, chol_smem>>>(bvec);
    trsm_kernel<<<dim3(8, BATCH), 256, trsm_smem>>>(A);
    admm_kernel<<<BATCH, 256, admm_smem>>>(x, mask, out);
}

// round 7
// speedup vs baseline: 1.5434x; 1.1788x over previous
#include <cuda_runtime.h>
#include <cuda_fp16.h>
#include <math.h>

#define BATCH 256
#define MDIM  256
#define VDIM  1024
#define JITTER 1e-6f
#define RING_SLOTS 4

// ------------------------- device scratch (no allocs allowed) -------------------------
__device__ float  g_W  [(size_t)BATCH * MDIM * VDIM];   // 256 MB : W = L^{-1} A (fp32)
__device__ __half g_Wh [(size_t)BATCH * MDIM * VDIM];   // 128 MB : W in fp16 (iteration copy)
__device__ float  g_L  [(size_t)BATCH * MDIM * MDIM];   // 64 MB  : G, then L (lower)
__device__ float  g_Ldi[(size_t)BATCH * 4 * 64 * 64];   // 4 MB   : inv of diag 64x64 blocks of L
__device__ float  g_c  [(size_t)BATCH * MDIM];          // L^{-1} b

// ======================= K1: G = A A^T + jitter*I (3 lower 128x128 tiles) =======================
__global__ __launch_bounds__(256, 2) void syrk_kernel(const float* __restrict__ A)
{
    __shared__ float As[2][16][132];
    __shared__ float Bs[2][16][132];
    int t = blockIdx.x, b = blockIdx.y;
    int ti = (t == 0) ? 0 : 1;
    int tj = (t == 2) ? 1 : 0;

    const float* Abase = A + (size_t)b * (MDIM * VDIM);
    const float* Ai = Abase + (size_t)(ti * 128) * VDIM;
    const float* Aj = Abase + (size_t)(tj * 128) * VDIM;

    int tid = threadIdx.x;
    int tx = tid & 15, ty = tid >> 4;
    int lrow = tid >> 2, lf = tid & 3;

    float acc[8][8];
#pragma unroll
    for (int i = 0; i < 8; i++)
#pragma unroll
        for (int j = 0; j < 8; j++) acc[i][j] = 0.f;

    float4 pa0 = __ldcs((const float4*)&Ai[(size_t)lrow * VDIM + 4 * lf]);
    float4 pa1 = __ldcs((const float4*)&Ai[(size_t)(lrow + 64) * VDIM + 4 * lf]);
    float4 pb0 = __ldcs((const float4*)&Aj[(size_t)lrow * VDIM + 4 * lf]);
    float4 pb1 = __ldcs((const float4*)&Aj[(size_t)(lrow + 64) * VDIM + 4 * lf]);
    {
        float va[4] = {pa0.x, pa0.y, pa0.z, pa0.w};
        float vb[4] = {pa1.x, pa1.y, pa1.z, pa1.w};
        float vc[4] = {pb0.x, pb0.y, pb0.z, pb0.w};
        float vd[4] = {pb1.x, pb1.y, pb1.z, pb1.w};
#pragma unroll
        for (int c = 0; c < 4; c++) {
            As[0][4 * lf + c][lrow]      = va[c];
            As[0][4 * lf + c][lrow + 64] = vb[c];
            Bs[0][4 * lf + c][lrow]      = vc[c];
            Bs[0][4 * lf + c][lrow + 64] = vd[c];
        }
    }
    __syncthreads();

    int buf = 0;
    for (int kt = 0; kt < 64; kt++) {
        if (kt < 63) {
            int k0 = (kt + 1) * 16;
            pa0 = __ldcs((const float4*)&Ai[(size_t)lrow * VDIM + k0 + 4 * lf]);
            pa1 = __ldcs((const float4*)&Ai[(size_t)(lrow + 64) * VDIM + k0 + 4 * lf]);
            pb0 = __ldcs((const float4*)&Aj[(size_t)lrow * VDIM + k0 + 4 * lf]);
            pb1 = __ldcs((const float4*)&Aj[(size_t)(lrow + 64) * VDIM + k0 + 4 * lf]);
        }
#pragma unroll
        for (int kk = 0; kk < 16; kk++) {
            float4 alo = *(const float4*)&As[buf][kk][4 * ty];
            float4 ahi = *(const float4*)&As[buf][kk][64 + 4 * ty];
            float4 blo = *(const float4*)&Bs[buf][kk][4 * tx];
            float4 bhi = *(const float4*)&Bs[buf][kk][64 + 4 * tx];
            float ar[8] = {alo.x, alo.y, alo.z, alo.w, ahi.x, ahi.y, ahi.z, ahi.w};
            float br[8] = {blo.x, blo.y, blo.z, blo.w, bhi.x, bhi.y, bhi.z, bhi.w};
#pragma unroll
            for (int i = 0; i < 8; i++)
#pragma unroll
                for (int j = 0; j < 8; j++) acc[i][j] = fmaf(ar[i], br[j], acc[i][j]);
        }
        if (kt < 63) {
            int nb = buf ^ 1;
            float va[4] = {pa0.x, pa0.y, pa0.z, pa0.w};
            float vb[4] = {pa1.x, pa1.y, pa1.z, pa1.w};
            float vc[4] = {pb0.x, pb0.y, pb0.z, pb0.w};
            float vd[4] = {pb1.x, pb1.y, pb1.z, pb1.w};
#pragma unroll
            for (int c = 0; c < 4; c++) {
                As[nb][4 * lf + c][lrow]      = va[c];
                As[nb][4 * lf + c][lrow + 64] = vb[c];
                Bs[nb][4 * lf + c][lrow]      = vc[c];
                Bs[nb][4 * lf + c][lrow + 64] = vd[c];
            }
            __syncthreads();
            buf = nb;
        }
    }

    float* Gb = g_L + (size_t)b * (MDIM * MDIM);
#pragma unroll
    for (int rr = 0; rr < 8; rr++) {
        int rloc = (rr < 4) ? (4 * ty + rr) : (64 + 4 * ty + rr - 4);
        int grow = ti * 128 + rloc;
#pragma unroll
        for (int q = 0; q < 2; q++) {
            int cloc = 4 * tx + 64 * q;
            float4 v = make_float4(acc[rr][4 * q + 0], acc[rr][4 * q + 1],
                                   acc[rr][4 * q + 2], acc[rr][4 * q + 3]);
            if (ti == tj) {
                int d = rloc - cloc;
                if (d >= 0 && d < 4) ((float*)&v)[d] += JITTER;
            }
            *(float4*)&Gb[(size_t)grow * MDIM + tj * 128 + cloc] = v;
        }
    }
}

// ====== K2: per-batch Cholesky in packed SMEM + diag-block inverses + c = L^{-1} b ======
#define PIDX(i, j) ((i) * ((i) + 1) / 2 + (j))
__global__ __launch_bounds__(256) void chol_kernel(const float* __restrict__ b_in)
{
    extern __shared__ float sm2[];
    float* P    = sm2;
    float* Inv  = sm2 + 32896;
    float* tst  = Inv + 4 * 64 * 65;
    float* cvec = tst + 64;
    float* colk = cvec + 256;

    int b = blockIdx.x, tid = threadIdx.x;
    int w = tid >> 5, lane = tid & 31;
    const float* Gb = g_L + (size_t)b * (MDIM * MDIM);

    {
        int i = tid, base = PIDX(i, 0);
        for (int j = 0; j <= i; j++) P[base + j] = Gb[i * MDIM + j];
    }
    __syncthreads();

    for (int k = 0; k < MDIM; k++) {
        if (tid == 0) P[PIDX(k, k)] = sqrtf(P[PIDX(k, k)]);
        __syncthreads();
        float dk = P[PIDX(k, k)];
        if (tid > k) {
            float v = P[PIDX(tid, 0) + k] / dk;
            P[PIDX(tid, 0) + k] = v;
            colk[tid] = v;
        }
        __syncthreads();
        for (int i = k + 1 + w; i < MDIM; i += 8) {
            float lik = colk[i];
            int base = PIDX(i, 0);
            for (int j = k + 1 + lane; j <= i; j += 32)
                P[base + j] = fmaf(-lik, colk[j], P[base + j]);
        }
        __syncthreads();
    }

    {
        int blk = tid >> 6, col = tid & 63, b0 = blk * 64;
        float* Ib = Inv + blk * 64 * 65;
        for (int i = 0; i < col; i++) Ib[i * 65 + col] = 0.f;
        for (int i = col; i < 64; i++) {
            int gi = b0 + i, gbase = PIDX(gi, 0);
            float s = (i == col) ? 1.f : 0.f;
            for (int k = col; k < i; k++) s = fmaf(-P[gbase + b0 + k], Ib[k * 65 + col], s);
            Ib[i * 65 + col] = s / P[gbase + gi];
        }
    }
    __syncthreads();

    {
        const float* bv = b_in + (size_t)b * MDIM;
        for (int blk = 0; blk < 4; blk++) {
            if (tid < 64) {
                int gi = blk * 64 + tid, gb = PIDX(gi, 0);
                float s = bv[gi];
                for (int j = 0; j < blk * 64; j++) s = fmaf(-P[gb + j], cvec[j], s);
                tst[tid] = s;
            }
            __syncthreads();
            if (tid < 64) {
                const float* Ib = Inv + blk * 64 * 65 + tid * 65;
                float s = 0.f;
                for (int k = 0; k < 64; k++) s = fmaf(Ib[k], tst[k], s);
                cvec[blk * 64 + tid] = s;
            }
            __syncthreads();
        }
    }

    {
        int i = tid, base = PIDX(i, 0);
        float* Lo = g_L + (size_t)b * (MDIM * MDIM) + i * MDIM;
        for (int j = 0; j <= i; j++) Lo[j] = P[base + j];

        int blk = tid >> 6, r = tid & 63;
        const float* Ib = Inv + blk * 64 * 65 + r * 65;
        float* o = g_Ldi + (((size_t)b * 4 + blk) * 64 + r) * 64;
        for (int k = 0; k < 64; k++) o[k] = Ib[k];

        g_c[(size_t)b * MDIM + tid] = cvec[tid];
    }
}

// =================== K3: W = L^{-1} A  (blocked trsm; writes fp32 + fp16 copies) ===================
__global__ __launch_bounds__(256, 2) void trsm_kernel(const float* __restrict__ A)
{
    extern __shared__ float sm3[];
    float* Tp = sm3;             // [64][132]
    float* Lb = sm3 + 8448;      // [2][16][68]
    float* Wt = Lb + 2176;       // [2][16][132]
    float* Db = sm3 + 8448;      // [64][68]  (overlaps Lb/Wt)

    int vt = blockIdx.x, b = blockIdx.y;
    int vc = vt * 128;
    int tid = threadIdx.x, tx = tid & 15, ty = tid >> 4;
    const float* Ab = A + (size_t)b * (MDIM * VDIM);
    const float* Lg = g_L + (size_t)b * (MDIM * MDIM);
    float* Wg = g_W + (size_t)b * (MDIM * VDIM);
    __half* Wh = g_Wh + (size_t)b * (MDIM * VDIM);

    int r4 = tid >> 2, f4 = tid & 3;
    int kkA = tid >> 5, cg = tid & 31;

    for (int i = 0; i < 4; i++) {
        float acc[4][8];
#pragma unroll
        for (int r = 0; r < 4; r++)
#pragma unroll
            for (int q = 0; q < 2; q++) {
                float4 av = __ldcs((const float4*)&Ab[(size_t)(i * 64 + 4 * ty + r) * VDIM + vc + 4 * tx + 64 * q]);
                acc[r][4 * q + 0] = av.x; acc[r][4 * q + 1] = av.y;
                acc[r][4 * q + 2] = av.z; acc[r][4 * q + 3] = av.w;
            }

        int nkt = 4 * i;
        if (nkt > 0) {
            float4 lv  = *(const float4*)&Lg[(size_t)(i * 64 + r4) * MDIM + 4 * f4];
            float4 wv0 = *(const float4*)&Wg[(size_t)(kkA)     * VDIM + vc + 4 * cg];
            float4 wv1 = *(const float4*)&Wg[(size_t)(kkA + 8) * VDIM + vc + 4 * cg];
            Lb[(4 * f4 + 0) * 68 + r4] = lv.x; Lb[(4 * f4 + 1) * 68 + r4] = lv.y;
            Lb[(4 * f4 + 2) * 68 + r4] = lv.z; Lb[(4 * f4 + 3) * 68 + r4] = lv.w;
            *(float4*)&Wt[kkA * 132 + 4 * cg] = wv0;
            *(float4*)&Wt[(kkA + 8) * 132 + 4 * cg] = wv1;
            __syncthreads();

            int buf = 0;
            for (int kt = 0; kt < nkt; kt++) {
                float4 lvn, wv0n, wv1n;
                if (kt + 1 < nkt) {
                    int k0 = (kt + 1) * 16;
                    lvn  = *(const float4*)&Lg[(size_t)(i * 64 + r4) * MDIM + k0 + 4 * f4];
                    wv0n = *(const float4*)&Wg[(size_t)(k0 + kkA)     * VDIM + vc + 4 * cg];
                    wv1n = *(const float4*)&Wg[(size_t)(k0 + kkA + 8) * VDIM + vc + 4 * cg];
                }
                const float* Lc = Lb + buf * 1088;
                const float* Wc = Wt + buf * 2112;
#pragma unroll
                for (int kk = 0; kk < 16; kk++) {
                    float4 a4 = *(const float4*)&Lc[kk * 68 + 4 * ty];
                    float4 w0 = *(const float4*)&Wc[kk * 132 + 4 * tx];
                    float4 w1 = *(const float4*)&Wc[kk * 132 + 64 + 4 * tx];
                    float ar[4] = {a4.x, a4.y, a4.z, a4.w};
                    float wv[8] = {w0.x, w0.y, w0.z, w0.w, w1.x, w1.y, w1.z, w1.w};
#pragma unroll
                    for (int r = 0; r < 4; r++)
#pragma unroll
                        for (int c = 0; c < 8; c++) acc[r][c] = fmaf(-ar[r], wv[c], acc[r][c]);
                }
                if (kt + 1 < nkt) {
                    int nb = buf ^ 1;
                    float* Ln = Lb + nb * 1088;
                    float* Wn = Wt + nb * 2112;
                    Ln[(4 * f4 + 0) * 68 + r4] = lvn.x; Ln[(4 * f4 + 1) * 68 + r4] = lvn.y;
                    Ln[(4 * f4 + 2) * 68 + r4] = lvn.z; Ln[(4 * f4 + 3) * 68 + r4] = lvn.w;
                    *(float4*)&Wn[kkA * 132 + 4 * cg] = wv0n;
                    *(float4*)&Wn[(kkA + 8) * 132 + 4 * cg] = wv1n;
                    __syncthreads();
                    buf = nb;
                }
            }
            __syncthreads();
        }

#pragma unroll
        for (int r = 0; r < 4; r++)
#pragma unroll
            for (int q = 0; q < 2; q++) {
                float4 o = make_float4(acc[r][4 * q + 0], acc[r][4 * q + 1],
                                       acc[r][4 * q + 2], acc[r][4 * q + 3]);
                *(float4*)&Tp[(4 * ty + r) * 132 + 4 * tx + 64 * q] = o;
            }
#pragma unroll
        for (int s = 0; s < 4; s++) {
            int n = tid + 256 * s;
            int r = n >> 4, f = n & 15;
            float4 dv = *(const float4*)&g_Ldi[(((size_t)b * 4 + i) * 64 + r) * 64 + 4 * f];
            Db[(4 * f + 0) * 68 + r] = dv.x; Db[(4 * f + 1) * 68 + r] = dv.y;
            Db[(4 * f + 2) * 68 + r] = dv.z; Db[(4 * f + 3) * 68 + r] = dv.w;
        }
        __syncthreads();

        float acc2[4][8];
#pragma unroll
        for (int r = 0; r < 4; r++)
#pragma unroll
            for (int c = 0; c < 8; c++) acc2[r][c] = 0.f;
#pragma unroll 16
        for (int kk = 0; kk < 64; kk++) {
            float4 a4 = *(const float4*)&Db[kk * 68 + 4 * ty];
            float4 t0 = *(const float4*)&Tp[kk * 132 + 4 * tx];
            float4 t1 = *(const float4*)&Tp[kk * 132 + 64 + 4 * tx];
            float ar[4] = {a4.x, a4.y, a4.z, a4.w};
            float tv[8] = {t0.x, t0.y, t0.z, t0.w, t1.x, t1.y, t1.z, t1.w};
#pragma unroll
            for (int r = 0; r < 4; r++)
#pragma unroll
                for (int c = 0; c < 8; c++) acc2[r][c] = fmaf(ar[r], tv[c], acc2[r][c]);
        }

#pragma unroll
        for (int r = 0; r < 4; r++)
#pragma unroll
            for (int q = 0; q < 2; q++) {
                float4 o = make_float4(acc2[r][4 * q + 0], acc2[r][4 * q + 1],
                                       acc2[r][4 * q + 2], acc2[r][4 * q + 3]);
                size_t off = (size_t)(i * 64 + 4 * ty + r) * VDIM + vc + 4 * tx + 64 * q;
                *(float4*)&Wg[off] = o;
                __half2 h01 = __floats2half2_rn(o.x, o.y);
                __half2 h23 = __floats2half2_rn(o.z, o.w);
                __half2 hh[2] = {h01, h23};
                *(uint2*)&Wh[off] = *(uint2*)hh;
            }
        __syncthreads();
    }
}

// =================== K5: fused ADMM loop (cp.async ring pipeline on fp16 W) ===================
// xk = 0.5*r - sum_m (0.5*s_m - c_m) w_m,   s_m = w_m . r
// smem: rsh 1024f | vp 8*1024f | cc 256f (37888 B) + ring 8 warps * 4 slots * 2048 B = 65536 B
//       -> 103424 B per CTA, 2 CTAs/SM.
// Per warp: lane L cp.asyncs its own 4x16B chunks of row j+3 into slot (j+3)&3, commit_group,
// wait_group 3, then consumes row j from slot j&3 via LDS.128. Producer lane == consumer lane
// -> no intra-warp sync; same-thread same-address ordering makes slot reuse race-free. Row
// sequence repeats each iteration so slot phase is continuous across iterations.
__device__ __forceinline__ void cp_async16(void* smem_dst, const void* gmem_src)
{
    unsigned dst = (unsigned)__cvta_generic_to_shared(smem_dst);
    asm volatile("cp.async.cg.shared.global [%0], [%1], 16;"
                 :: "r"(dst), "l"(gmem_src) : "memory");
}

__global__ __launch_bounds__(256, 2) void admm_kernel(
    const float* __restrict__ x_in, const int* __restrict__ mask,
    float* __restrict__ out)
{
    extern __shared__ __align__(16) unsigned char smraw[];
    float* rsh = (float*)smraw;              // 1024
    float* vp  = rsh + 1024;                 // 8*1024
    float* cc  = rsh + 9216;                 // 256
    __half* ring = (__half*)(smraw + 37888); // 8 warps * 4 slots * 1024 halfs

    int b = blockIdx.x, tid = threadIdx.x;
    int w = tid >> 5, lane = tid & 31;
    const __half* Whb = g_Wh + (size_t)b * (MDIM * VDIM);
    const float*  Wfb = g_W  + (size_t)b * (MDIM * VDIM);
    __half* ringw = ring + w * (RING_SLOTS * 1024);

    // --- prologue: prefetch rows 0,1,2 of this warp's set into slots 0,1,2 ---
#pragma unroll
    for (int r = 0; r < 3; r++) {
        const __half* grow = Whb + (size_t)(w * 32 + r) * VDIM;
        __half* slot = ringw + r * 1024;
#pragma unroll
        for (int q = 0; q < 4; q++) {
            int ch = lane + 32 * q;
            cp_async16(slot + ch * 8, grow + ch * 8);
        }
        asm volatile("cp.async.commit_group;" ::: "memory");
    }

    float4 xreg = *(const float4*)&x_in[(size_t)b * VDIM + 4 * tid];
    int4 m4 = *(const int4*)&mask[4 * tid];
    float4 ureg = make_float4(0.f, 0.f, 0.f, 0.f);
    float4 rown = xreg;   // this thread's own 4 entries of r (cols 4*tid..4*tid+3)
    cc[tid] = g_c[(size_t)b * MDIM + tid];
    *(float4*)&rsh[4 * tid] = xreg;

    for (int it = 0; it < 100; it++) {
        __syncthreads();   // r in SMEM ready; vp free for reuse
        // lane's 32 r-values: cols 256*q + 8*lane + c  (q=0..3, c=0..7)
        float rr[32];
#pragma unroll
        for (int q = 0; q < 4; q++) {
            float4 r0 = *(float4*)&rsh[256 * q + 8 * lane];
            float4 r1 = *(float4*)&rsh[256 * q + 8 * lane + 4];
            rr[8 * q + 0] = r0.x; rr[8 * q + 1] = r0.y; rr[8 * q + 2] = r0.z; rr[8 * q + 3] = r0.w;
            rr[8 * q + 4] = r1.x; rr[8 * q + 5] = r1.y; rr[8 * q + 6] = r1.z; rr[8 * q + 7] = r1.w;
        }
        float v[32];
#pragma unroll
        for (int c = 0; c < 32; c++) v[c] = 0.f;

        for (int j = 0; j < 32; j++) {
            // prefetch row (j+3)&31 into slot (j+3)&3
            {
                int pr = (j + 3) & 31;
                const __half* grow = Whb + (size_t)(w * 32 + pr) * VDIM;
                __half* slot = ringw + ((j + 3) & 3) * 1024;
#pragma unroll
                for (int q = 0; q < 4; q++) {
                    int ch = lane + 32 * q;
                    cp_async16(slot + ch * 8, grow + ch * 8);
                }
                asm volatile("cp.async.commit_group;" ::: "memory");
            }
            asm volatile("cp.async.wait_group 3;" ::: "memory");

            const __half* slot = ringw + (j & 3) * 1024;
            // dot pass
            float s = 0.f;
#pragma unroll
            for (int q = 0; q < 4; q++) {
                uint4 u = *(const uint4*)(slot + (lane + 32 * q) * 8);
                float2 f0 = __half22float2(*(__half2*)&u.x);
                float2 f1 = __half22float2(*(__half2*)&u.y);
                float2 f2 = __half22float2(*(__half2*)&u.z);
                float2 f3 = __half22float2(*(__half2*)&u.w);
                s = fmaf(f0.x, rr[8 * q + 0], s); s = fmaf(f0.y, rr[8 * q + 1], s);
                s = fmaf(f1.x, rr[8 * q + 2], s); s = fmaf(f1.y, rr[8 * q + 3], s);
                s = fmaf(f2.x, rr[8 * q + 4], s); s = fmaf(f2.y, rr[8 * q + 5], s);
                s = fmaf(f3.x, rr[8 * q + 6], s); s = fmaf(f3.y, rr[8 * q + 7], s);
            }
#pragma unroll
            for (int off = 16; off > 0; off >>= 1) s += __shfl_xor_sync(0xffffffffu, s, off);
            float coef = 0.5f * s - cc[(w << 5) + j];
            // axpy pass (reload from SMEM, convert again)
#pragma unroll
            for (int q = 0; q < 4; q++) {
                uint4 u = *(const uint4*)(slot + (lane + 32 * q) * 8);
                float2 f0 = __half22float2(*(__half2*)&u.x);
                float2 f1 = __half22float2(*(__half2*)&u.y);
                float2 f2 = __half22float2(*(__half2*)&u.z);
                float2 f3 = __half22float2(*(__half2*)&u.w);
                v[8 * q + 0] = fmaf(coef, f0.x, v[8 * q + 0]); v[8 * q + 1] = fmaf(coef, f0.y, v[8 * q + 1]);
                v[8 * q + 2] = fmaf(coef, f1.x, v[8 * q + 2]); v[8 * q + 3] = fmaf(coef, f1.y, v[8 * q + 3]);
                v[8 * q + 4] = fmaf(coef, f2.x, v[8 * q + 4]); v[8 * q + 5] = fmaf(coef, f2.y, v[8 * q + 5]);
                v[8 * q + 6] = fmaf(coef, f3.x, v[8 * q + 6]); v[8 * q + 7] = fmaf(coef, f3.y, v[8 * q + 7]);
            }
        }
        // partials to SMEM: vp[w*1024 + col], col = 256*q + 8*lane + c
#pragma unroll
        for (int q = 0; q < 4; q++) {
            *(float4*)&vp[w * 1024 + 256 * q + 8 * lane]     = make_float4(v[8 * q + 0], v[8 * q + 1], v[8 * q + 2], v[8 * q + 3]);
            *(float4*)&vp[w * 1024 + 256 * q + 8 * lane + 4] = make_float4(v[8 * q + 4], v[8 * q + 5], v[8 * q + 6], v[8 * q + 7]);
        }
        __syncthreads();

        float4 vs = make_float4(0.f, 0.f, 0.f, 0.f);
#pragma unroll
        for (int ww = 0; ww < 8; ww++) {
            float4 p = *(float4*)&vp[ww * 1024 + 4 * tid];
            vs.x += p.x; vs.y += p.y; vs.z += p.z; vs.w += p.w;
        }
        float4 xk;
        xk.x = 0.5f * rown.x - vs.x;
        xk.y = 0.5f * rown.y - vs.y;
        xk.z = 0.5f * rown.z - vs.z;
        xk.w = 0.5f * rown.w - vs.w;

        float wv, zv;
        wv = xk.x + ureg.x; zv = (m4.x > 0) ? fminf(wv, 0.f) : wv; ureg.x = wv - zv; rown.x = xreg.x + zv - ureg.x;
        wv = xk.y + ureg.y; zv = (m4.y > 0) ? fminf(wv, 0.f) : wv; ureg.y = wv - zv; rown.y = xreg.y + zv - ureg.y;
        wv = xk.z + ureg.z; zv = (m4.z > 0) ? fminf(wv, 0.f) : wv; ureg.z = wv - zv; rown.z = xreg.z + zv - ureg.z;
        wv = xk.w + ureg.w; zv = (m4.w > 0) ? fminf(wv, 0.f) : wv; ureg.w = wv - zv; rown.w = xreg.w + zv - ureg.w;
        *(float4*)&rsh[4 * tid] = rown;
    }

    // drain outstanding cp.async groups before the final pass reuses nothing but keeps state sane
    asm volatile("cp.async.wait_group 0;" ::: "memory");

    // --- final pass: exact fp32 W applied to converged r (output iterate) ---
    __syncthreads();
    {
        float rr[32];
#pragma unroll
        for (int q = 0; q < 4; q++) {
            float4 r0 = *(float4*)&rsh[256 * q + 8 * lane];
            float4 r1 = *(float4*)&rsh[256 * q + 8 * lane + 4];
            rr[8 * q + 0] = r0.x; rr[8 * q + 1] = r0.y; rr[8 * q + 2] = r0.z; rr[8 * q + 3] = r0.w;
            rr[8 * q + 4] = r1.x; rr[8 * q + 5] = r1.y; rr[8 * q + 6] = r1.z; rr[8 * q + 7] = r1.w;
        }
        float v[32];
#pragma unroll
        for (int c = 0; c < 32; c++) v[c] = 0.f;

        for (int j = 0; j < 32; j++) {
            int m = (w << 5) + j;
            const float4* row = (const float4*)(Wfb + (size_t)m * VDIM);
            float af[32];
#pragma unroll
            for (int q = 0; q < 4; q++) {
                float4 a0 = __ldcs(&row[2 * (lane + 32 * q)]);
                float4 a1 = __ldcs(&row[2 * (lane + 32 * q) + 1]);
                af[8 * q + 0] = a0.x; af[8 * q + 1] = a0.y; af[8 * q + 2] = a0.z; af[8 * q + 3] = a0.w;
                af[8 * q + 4] = a1.x; af[8 * q + 5] = a1.y; af[8 * q + 6] = a1.z; af[8 * q + 7] = a1.w;
            }
            float s = 0.f;
#pragma unroll
            for (int c = 0; c < 32; c++) s = fmaf(af[c], rr[c], s);
#pragma unroll
            for (int off = 16; off > 0; off >>= 1) s += __shfl_xor_sync(0xffffffffu, s, off);
            float coef = 0.5f * s - cc[m];
#pragma unroll
            for (int c = 0; c < 32; c++) v[c] = fmaf(coef, af[c], v[c]);
        }
#pragma unroll
        for (int q = 0; q < 4; q++) {
            *(float4*)&vp[w * 1024 + 256 * q + 8 * lane]     = make_float4(v[8 * q + 0], v[8 * q + 1], v[8 * q + 2], v[8 * q + 3]);
            *(float4*)&vp[w * 1024 + 256 * q + 8 * lane + 4] = make_float4(v[8 * q + 4], v[8 * q + 5], v[8 * q + 6], v[8 * q + 7]);
        }
        __syncthreads();

        float4 vs = make_float4(0.f, 0.f, 0.f, 0.f);
#pragma unroll
        for (int ww = 0; ww < 8; ww++) {
            float4 p = *(float4*)&vp[ww * 1024 + 4 * tid];
            vs.x += p.x; vs.y += p.y; vs.z += p.z; vs.w += p.w;
        }
        float4 xk;
        xk.x = 0.5f * rown.x - vs.x;
        xk.y = 0.5f * rown.y - vs.y;
        xk.z = 0.5f * rown.z - vs.z;
        xk.w = 0.5f * rown.w - vs.w;
        *(float4*)&out[(size_t)b * VDIM + 4 * tid] = xk;
    }
}

// ======================================= launch =======================================
extern "C" void kernel_launch(void* const* d_in, const int* in_sizes, int n_in,
                              void* d_out, int out_size)
{
    (void)in_sizes; (void)n_in; (void)out_size;
    const float* x    = (const float*)d_in[0];
    const float* bvec = (const float*)d_in[1];
    const float* A    = (const float*)d_in[2];
    const int*   mask = (const int*)d_in[3];
    float* out = (float*)d_out;

    size_t chol_smem = (size_t)(32896 + 4 * 64 * 65 + 64 + 256 + 256) * sizeof(float); // 200448 B
    size_t trsm_smem = (size_t)(8448 + 2176 + 4224) * sizeof(float);                   // 59392 B
    size_t admm_smem = (size_t)37888 + (size_t)8 * RING_SLOTS * 1024 * sizeof(__half); // 103424 B

    cudaFuncSetAttribute((const void*)chol_kernel, cudaFuncAttributeMaxDynamicSharedMemorySize, (int)chol_smem);
    cudaFuncSetAttribute((const void*)trsm_kernel, cudaFuncAttributeMaxDynamicSharedMemorySize, (int)trsm_smem);
    cudaFuncSetAttribute((const void*)admm_kernel, cudaFuncAttributeMaxDynamicSharedMemorySize, (int)admm_smem);

    syrk_kernel<<<dim3(3, BATCH), 256>>>(A);
    chol_kernel<<<BATCH, 256, chol_smem>>>(bvec);
    trsm_kernel<<<dim3(8, BATCH), 256, trsm_smem>>>(A);
    admm_kernel<<<BATCH, 256, admm_smem>>>(x, mask, out);
}